// round 15
// baseline (speedup 1.0000x reference)
#include <cuda_runtime.h>
#include <math.h>
#include <float.h>

typedef unsigned long long ull;

#define Ad 96
#define Wd 96
#define Cc 24
#define Bq 8
#define BCn 192
#define AW 9216
#define CHUNKS 6
#define CROWS 16
#define CCOLS 32
#define Fh 32

#define STPB 256
#define MTPB 384

#define SETR (BCn * 768)
#define SETC (BCn * 768)
#define SETT (BCn * 8)
#define SETM (BCn * 32)

// ---------------- device scratch ----------------
__device__ float    g_h[(size_t)BCn * Fh * AW];   // h: [bc][f][pos] fp32
__device__ double   g_rowsum[2 * SETR];
__device__ double   g_colsum[2 * SETC];
__device__ double   g_tot[2 * SETT];
__device__ unsigned g_hmax[2 * SETM];             // encoded-uint max
__device__ double   g_sq[BCn * Fh];
__device__ double   g_mean[BCn];
__device__ double   g_istd[BCn];
// PWL tables for mlp0: 129 segments
__device__ double g_tsort[128];
__device__ double g_A[129][32];
__device__ double g_B[129][32];

// ---------------- packed fp32 helpers (asm: fast-math-proof) ----------------
#define NEG1P 0xBF800000BF800000ULL   /* {-1.0f, -1.0f} */
#define SGN2  0x8000000080000000ULL

__device__ __forceinline__ float lof(ull v) { return __uint_as_float((unsigned)v); }
__device__ __forceinline__ float hif(ull v) { return __uint_as_float((unsigned)(v >> 32)); }
__device__ __forceinline__ ull dup2(float x) { ull r; asm("mov.b64 %0,{%1,%1};" : "=l"(r) : "f"(x)); return r; }
__device__ __forceinline__ ull mk2(float x, float y) { ull r; asm("mov.b64 %0,{%1,%2};" : "=l"(r) : "f"(x), "f"(y)); return r; }
__device__ __forceinline__ ull neg2(ull a) { return a ^ SGN2; }
__device__ __forceinline__ ull mul2(ull a, ull b) {
    ull d; asm("mul.rn.f32x2 %0,%1,%2;" : "=l"(d) : "l"(a), "l"(b)); return d;
}
__device__ __forceinline__ ull add2(ull a, ull b) {
    ull d; asm("add.rn.f32x2 %0,%1,%2;" : "=l"(d) : "l"(a), "l"(b)); return d;
}
__device__ __forceinline__ ull fma2(ull a, ull b, ull c) {
    ull d; asm("fma.rn.f32x2 %0,%1,%2,%3;" : "=l"(d) : "l"(a), "l"(b), "l"(c)); return d;
}

// df MAC, Knuth TwoSum (exact; precompute paths)
__device__ __forceinline__ void df_mac(ull& S, ull& L, ull rh, ull rl, ull w) {
    const ull N1 = NEG1P;
    ull p  = mul2(rh, w);
    ull e  = fma2(rh, w, neg2(p));
    e      = fma2(rl, w, e);
    ull s1 = add2(S, p);
    ull ap = fma2(p, N1, s1);
    ull bp = fma2(ap, N1, s1);
    ull ea = fma2(ap, N1, S);
    ull eb = fma2(bp, N1, p);
    ull er = add2(ea, eb);
    L      = add2(L, er);
    L      = add2(L, e);
    S      = s1;
}
// df MAC, Fast2Sum compensation (8 ops; inner-loop L2).
// EXACT TwoProd residual is load-bearing (R12 post-mortem);
// only the addition compensation is approximate (loss when |p|>|S|: rare).
__device__ __forceinline__ void df_macf(ull& S, ull& L, ull rh, ull rl, ull w) {
    const ull N1 = NEG1P;
    ull p  = mul2(rh, w);
    ull e  = fma2(rh, w, neg2(p));
    e      = fma2(rl, w, e);
    ull s1 = add2(S, p);
    ull z  = fma2(S, N1, s1);    // s1 - S
    ull e2 = fma2(z, N1, p);     // p - z
    L      = add2(L, e2);
    L      = add2(L, e);
    S      = s1;
}
// (S,L) += (bh, bl) df + df, Knuth (exact)
__device__ __forceinline__ void df_add(ull& S, ull& L, ull bh, ull bl) {
    const ull N1 = NEG1P;
    ull s1 = add2(S, bh);
    ull ap = fma2(bh, N1, s1);
    ull bp = fma2(ap, N1, s1);
    ull ea = fma2(ap, N1, S);
    ull eb = fma2(bp, N1, bh);
    ull er = add2(ea, eb);
    L      = add2(L, bl);
    L      = add2(L, er);
    S      = s1;
}

__device__ __forceinline__ unsigned encf(float x) {
    int i = __float_as_int(x);
    return (i >= 0) ? ((unsigned)i | 0x80000000u) : ~(unsigned)i;
}
__device__ __forceinline__ float decf(unsigned u) {
    int i = (u & 0x80000000u) ? (int)(u & 0x7fffffffu) : ~(int)u;
    return __int_as_float(i);
}
#define ENC_NEGMAX 0x00800000u
#define ENC_ZERO   0x80000000u

__device__ __forceinline__ double warpsumd(double v) {
    v += __shfl_xor_sync(0xffffffffu, v, 16);
    v += __shfl_xor_sync(0xffffffffu, v, 8);
    v += __shfl_xor_sync(0xffffffffu, v, 4);
    v += __shfl_xor_sync(0xffffffffu, v, 2);
    v += __shfl_xor_sync(0xffffffffu, v, 1);
    return v;
}
__device__ __forceinline__ float warpmaxf(float v) {
    v = fmaxf(v, __shfl_xor_sync(0xffffffffu, v, 16));
    v = fmaxf(v, __shfl_xor_sync(0xffffffffu, v, 8));
    v = fmaxf(v, __shfl_xor_sync(0xffffffffu, v, 4));
    v = fmaxf(v, __shfl_xor_sync(0xffffffffu, v, 2));
    v = fmaxf(v, __shfl_xor_sync(0xffffffffu, v, 1));
    return v;
}

// Accurate fp32 sin (1-2 ulp), fast-math-proof.
__device__ __forceinline__ float sin_acc(float x) {
    float n = rintf(x * 0.318309886183790672f);
    float r = fmaf(n, -3.140625f, x);
    r = fmaf(n, -9.67502593994140625e-4f, r);
    r = fmaf(n, -1.50995799097837643e-7f, r);
    float r2 = r * r;
    float p = fmaf(r2, 2.60831598e-06f, -1.98106907e-04f);
    p = fmaf(r2, p, 8.33330786e-03f);
    p = fmaf(r2, p, -1.66666597e-01f);
    float s = fmaf(r * r2, p, r);
    int ni = (int)n;
    return __int_as_float(__float_as_int(s) ^ ((ni & 1) << 31));
}

// ---------------- per-matrix mean / inv-std + g_sq zero ----------------
__global__ void stats_kernel(const float* __restrict__ x,
                             const int* __restrict__ rlp, const int* __restrict__ clp) {
    int bc = blockIdx.x, tid = threadIdx.x;
    int rl = rlp[bc], cl = clp[bc];
    double s = 0.0, s2 = 0.0;
    const float* xp = x + (size_t)bc * AW;
    for (int p = tid; p < AW; p += 256) {
        int a = p / Wd, w = p - a * Wd;
        if (a < rl && w < cl) { double v = (double)xp[p]; s += v; s2 += v * v; }
    }
    __shared__ double sh[256], sh2[256];
    sh[tid] = s; sh2[tid] = s2;
    __syncthreads();
    for (int o = 128; o; o >>= 1) {
        if (tid < o) { sh[tid] += sh[tid + o]; sh2[tid] += sh2[tid + o]; }
        __syncthreads();
    }
    if (tid == 0) {
        double n = (double)rl * (double)cl;
        double mean = sh[0] / n;
        double var = (sh2[0] - n * mean * mean) / (n - 1.0);
        g_mean[bc] = mean;
        g_istd[bc] = 1.0 / fmax(sqrt(fmax(var, 0.0)), 1e-12);
    }
    if (tid < 32) g_sq[bc * 32 + tid] = 0.0;
}

// ---------------- zero one accumulator set (now includes rowsum) ----------------
__global__ void zero_set(int s) {
    int i = blockIdx.x * 256 + threadIdx.x;   // 576*256 = SETC = SETR
    g_colsum[s * SETC + i] = 0.0;
    g_rowsum[s * SETR + i] = 0.0;
    if (i < SETT) g_tot[s * SETT + i] = 0.0;
    if (i < SETM) g_hmax[s * SETM + i] = ENC_NEGMAX;
}

// ---------------- mlp0 PWL precompute ----------------
__global__ void mlp0_pre(const float* __restrict__ w01, const float* __restrict__ b01,
                         const float* __restrict__ w2, const float* __restrict__ b2) {
    __shared__ double tval[128];
    __shared__ int order[128];
    __shared__ double tsort[128];
    int j = threadIdx.x;   // 128 threads
    double wj = (double)w01[j], bj = (double)b01[j];
    double t = (wj != 0.0) ? (-bj / wj) : DBL_MAX;
    tval[j] = t;
    __syncthreads();
    int rank = 0;
    for (int k = 0; k < 128; k++) {
        double tk = tval[k];
        rank += (tk < t) || (tk == t && k < j);
    }
    order[rank] = j;
    tsort[rank] = t;
    __syncthreads();
    g_tsort[j] = tsort[j];
    if (j < 32) {
        int f = j;
        double A = 0.0, B = (double)b2[f];
        for (int k = 0; k < 128; k++) {
            double wk = (double)w01[k], bk = (double)b01[k];
            if (wk < 0.0 || (wk == 0.0 && bk > 0.0)) {
                double w2v = (double)w2[k * 32 + f];
                A += wk * w2v; B += bk * w2v;
            }
        }
        g_A[0][f] = A; g_B[0][f] = B;
        for (int s = 1; s <= 128; s++) {
            int k = order[s - 1];
            double wk = (double)w01[k], bk = (double)b01[k];
            double w2v = (double)w2[k * 32 + f];
            if (wk > 0.0)      { A += wk * w2v; B += bk * w2v; }
            else if (wk < 0.0) { A -= wk * w2v; B -= bk * w2v; }
            g_A[s][f] = A; g_B[s][f] = B;
        }
    }
}

// ---------------- mlp0 eval: PWL + fused stack-0 reduction epilogue (writes set 0) ----------------
#define EVD_PWL (128 + 2 * 129 * 33)
#define EVD_ROW EVD_PWL
#define EVD_COL (EVD_ROW + 128)
#define EVD_TOT (EVD_COL + 768)
#define EVD_MAX (EVD_TOT + 8)
#define EV_SMEM ((EVD_MAX + 16) * 8)
__global__ void __launch_bounds__(MTPB, 1)
mlp0_eval(const float* __restrict__ x,
          const int* __restrict__ rlp, const int* __restrict__ clp) {
    int bid = blockIdx.x;
    int bc = bid / CHUNKS, chunk = bid - (bid / CHUNKS) * CHUNKS;
    int a0 = chunk * CROWS;
    int tid = threadIdx.x, lane = tid & 31;
    int rl = rlp[bc], cl = clp[bc];
    if (a0 >= rl) {
        if (tid < 32) atomicMax(&g_hmax[bc * 32 + tid], ENC_ZERO);
        return;
    }
    extern __shared__ double smd[];
    double* s_t = smd;
    double* s_A = smd + 128;
    double* s_B = s_A + 129 * 33;
    double*   s_erow = smd + EVD_ROW;
    double*   s_ecol = smd + EVD_COL;
    double*   s_etot = smd + EVD_TOT;
    unsigned* s_emax = (unsigned*)(smd + EVD_MAX);
    bool hasInv = (rl < a0 + CROWS) || (cl < Wd);
    for (int e = tid; e < 129 * 32; e += MTPB) {
        int s = e >> 5, f = e & 31;
        s_A[s * 33 + f] = g_A[s][f];
        s_B[s * 33 + f] = g_B[s][f];
    }
    if (tid < 128) s_t[tid] = g_tsort[tid];
    for (int e = tid; e < 128; e += MTPB) s_erow[e] = 0.0;
    for (int e = tid; e < 768; e += MTPB) s_ecol[e] = 0.0;
    if (tid < 8) s_etot[tid] = 0.0;
    if (tid < 32) s_emax[tid] = hasInv ? ENC_ZERO : ENC_NEGMAX;
    __syncthreads();

    double meand = g_mean[bc], istdd = g_istd[bc];
    const float* xp = x + (size_t)bc * AW + a0 * Wd;
    float* hbc = g_h + (size_t)bc * Fh * AW + a0 * Wd;

    double totg[8];
    float rmax[32];
#pragma unroll
    for (int k = 0; k < 8; k++) totg[k] = 0.0;
#pragma unroll
    for (int f = 0; f < 32; f++) rmax[f] = -FLT_MAX;

    for (int it = 0; it < 4; ++it) {
        int p = it * MTPB + tid;
        int al = p / Wd, w = p - al * Wd;
        bool valid = (a0 + al < rl) && (w < cl);
        if (!__any_sync(0xffffffffu, valid)) continue;
        float xnf = valid ? (float)(((double)xp[p] - meand) * istdd) : 0.f;
        double xd = (double)xnf;
        int lo = 0, hi = 128;
#pragma unroll
        for (int st = 0; st < 7; st++) {
            int mid = (lo + hi) >> 1;
            bool c = s_t[mid] < xd;
            lo = c ? mid + 1 : lo;
            hi = c ? hi : mid;
        }
        const double* Ar = s_A + lo * 33;
        const double* Br = s_B + lo * 33;
        float hv[32];
#pragma unroll
        for (int f = 0; f < 32; f++) {
            double o = fma(Ar[f], xd, Br[f]);
            hv[f] = valid ? (float)o : 0.f;
            hbc[(size_t)f * AW + p] = hv[f];
        }
#pragma unroll
        for (int k = 0; k < 8; k++) {
            float y1 = sin_acc(hv[4 * k + 1]);
            float y2 = sin_acc(hv[4 * k + 2]);
            float y3 = sin_acc(hv[4 * k + 3]);
            totg[k] += (double)y3;
            atomicAdd(&s_ecol[k * 96 + w], (double)y2);
            double srw = warpsumd((double)y1);
            if (lane == 0) atomicAdd(&s_erow[al * 8 + k], srw);
        }
#pragma unroll
        for (int f = 0; f < 32; f++) rmax[f] = fmaxf(rmax[f], hv[f]);
    }
#pragma unroll
    for (int k = 0; k < 8; k++) {
        double s = warpsumd(totg[k]);
        if (lane == 0) atomicAdd(&s_etot[k], s);
    }
#pragma unroll
    for (int f = 0; f < 32; f++) {
        float m = warpmaxf(rmax[f]);
        if (lane == 0) atomicMax(&s_emax[f], encf(m));
    }
    __syncthreads();
    for (int e = tid; e < 128; e += MTPB) g_rowsum[bc * 768 + a0 * 8 + e] = s_erow[e];
    for (int e = tid; e < 768; e += MTPB) {
        int wi2 = e >> 3, kk = e & 7;
        atomicAdd(&g_colsum[bc * 768 + e], s_ecol[kk * 96 + wi2]);
    }
    if (tid < 8) atomicAdd(&g_tot[bc * 8 + tid], s_etot[tid]);
    if (tid < 32) atomicMax(&g_hmax[bc * 32 + tid], s_emax[tid]);
}

// ---------------- one equivariant stack: 16 rows x 32 cols per block, 2 CTAs/SM ----------------
// smem float offsets
#define SK_W1   0        /* 8192 */
#define SK_W2   8192     /* 4096 */
#define SK_CROW 12288    /* 16*65 ull2 = 4160 */
#define SK_COLT 16448    /* 32*65 ull2 = 8320 */
#define SK_CSD  24768    /* float2 x256 = 512 */
#define SK_RSD  25280    /* float2 x128 = 256 */
#define SK_BASE 25536    /* double x128 = 256 */
#define SK_TT   25792    /* double x8 = 16 */
#define SK_HM   25808    /* 32 */
#define SK_B1   25840    /* 128 */
#define SK_B2   25968    /* 32 */
#define SE_ROW  26000    /* double x128 = 256 */
#define SE_COL  26256    /* double x256 = 512 */
#define SE_TOT  26768    /* double x8 = 16 */
#define SE_MAX  26784    /* 32 u32 */
#define SK_W1E0 26816    /* 64*8 ull = 1024 */
#define SK_TOTF 27840
#define STACK_SMEM (SK_TOTF * 4)

template <bool LAST>
__global__ void __launch_bounds__(STPB, 2)
stack_kernel(const float* __restrict__ w1g, const float* __restrict__ b1g,
             const float* __restrict__ w2g, const float* __restrict__ b2g,
             const int* __restrict__ rlp, const int* __restrict__ clp, int ri) {
    int bid = blockIdx.x;
    int bc = bid / 18, rem = bid - (bid / 18) * 18;
    int rchunk = rem / 3, cchunk = rem - (rem / 3) * 3;
    int a0 = rchunk * CROWS, c0 = cchunk * CCOLS;
    int tid = threadIdx.x, lane = tid & 31;
    int rl = rlp[bc], cl = clp[bc];
    int wi = 1 - ri;
    if (a0 >= rl || c0 >= cl) {   // block region entirely zero h
        if (!LAST && tid < 32) atomicMax(&g_hmax[wi * SETM + bc * 32 + tid], ENC_ZERO);
        return;
    }
    int b = bc / Cc;

    extern __shared__ float smf[];
    float*      w1s  = smf + SK_W1;
    float*      w2s  = smf + SK_W2;
    ulonglong2* crw  = (ulonglong2*)(smf + SK_CROW);
    ulonglong2* ctw  = (ulonglong2*)(smf + SK_COLT);
    float2*     csd  = (float2*)(smf + SK_CSD);      // [wl][k], 32 cols
    float2*     rsd  = (float2*)(smf + SK_RSD);
    double*     based= (double*)(smf + SK_BASE);
    double*     ttd  = (double*)(smf + SK_TT);
    float*      hmf  = smf + SK_HM;
    float*      b1f  = smf + SK_B1;
    float*      b2f  = smf + SK_B2;
    double*     s_erow = (double*)(smf + SE_ROW);
    double*     s_ecol = (double*)(smf + SE_COL);    // [k][wl], 32 cols
    double*     s_etot = (double*)(smf + SE_TOT);
    unsigned*   s_emax = (unsigned*)(smf + SE_MAX);
    ull*        w1e0 = (ull*)(smf + SK_W1E0);        // [j2][k]
    bool hasInv = (rl < a0 + CROWS) || (cl < c0 + CCOLS);

    for (int e = tid; e < 8192; e += STPB) w1s[e] = w1g[e];
    for (int e = tid; e < 4096; e += STPB) w2s[e] = w2g[e];
    if (tid < 128) b1f[tid] = b1g[tid];
    if (tid < 32)  b2f[tid] = b2g[tid];
    for (int e = tid; e < 256; e += STPB) {   // col sums for this block's 32 cols
        int wl = e >> 3, k = e & 7;
        double v = g_colsum[ri * SETC + bc * 768 + (c0 + wl) * 8 + k];
        float hi = (float)v;
        csd[e] = make_float2(hi, (float)(v - (double)hi));
    }
    if (tid < 128) {
        double v = g_rowsum[ri * SETR + bc * 768 + a0 * 8 + tid];
        float hi = (float)v;
        rsd[tid] = make_float2(hi, (float)(v - (double)hi));
    }
    if (tid < 8) ttd[tid] = g_tot[ri * SETT + bc * 8 + tid];
    if (tid < 32) {
        float m = -FLT_MAX;
        for (int c = 0; c < Cc; c++) m = fmaxf(m, decf(g_hmax[ri * SETM + (b * Cc + c) * 32 + tid]));
        hmf[tid] = m;
    }
    if (!LAST) {
        for (int e = tid; e < 128; e += STPB) s_erow[e] = 0.0;
        for (int e = tid; e < 256; e += STPB) s_ecol[e] = 0.0;
        if (tid < 8) s_etot[tid] = 0.0;
        if (tid < 32) s_emax[tid] = hasInv ? ENC_ZERO : ENC_NEGMAX;
    } else {
        if (tid < 32) s_erow[tid] = 0.0;   // reused as s_sq
    }
    __syncthreads();
    if (tid < 128) {   // base[j] = b1 + tot-term + max-term (fp64)
        double acc = (double)b1f[tid];
#pragma unroll
        for (int k = 0; k < 8; k++) acc = fma(ttd[k], (double)w1s[(24 + k) * 128 + tid], acc);
#pragma unroll
        for (int f = 0; f < 32; f++) acc = fma((double)hmf[f], (double)w1s[(32 + f) * 128 + tid], acc);
        based[tid] = acc;
    }
    // repack w1 e0 rows: w1e0[j2*8 + k] = {w1[k][2j2], w1[k][2j2+1]} (bit-identical values)
    for (int e = tid; e < 512; e += STPB) {
        int j2 = e >> 3, k = e & 7;
        w1e0[e] = ((const ull*)(w1s + k * 128))[j2];
    }
    __syncthreads();
    // colt df: [wl][j2] = sum_k cs_df[wl][k] * w1[16+k][j] (exact Knuth)
    for (int e = tid; e < 2048; e += STPB) {
        int wl = e >> 6, j2 = e & 63;
        ull S = 0ull, L = 0ull;
#pragma unroll
        for (int k = 0; k < 8; k++) {
            float2 c = csd[wl * 8 + k];
            df_mac(S, L, dup2(c.x), dup2(c.y), ((const ull*)(w1s + (16 + k) * 128))[j2]);
        }
        ctw[wl * 65 + j2] = make_ulonglong2(S, L);
    }
    // crow df: [r][j2] = base + sum_k rs_df[r][k] * w1[8+k][j] (exact Knuth)
    for (int e = tid; e < 1024; e += STPB) {
        int r = e >> 6, j2 = e & 63;
        double b0 = based[2 * j2], b1v = based[2 * j2 + 1];
        float bh0 = (float)b0, bh1 = (float)b1v;
        ull S = mk2(bh0, bh1);
        ull L = mk2((float)(b0 - (double)bh0), (float)(b1v - (double)bh1));
#pragma unroll
        for (int k = 0; k < 8; k++) {
            float2 rr = rsd[r * 8 + k];
            df_mac(S, L, dup2(rr.x), dup2(rr.y), ((const ull*)(w1s + (8 + k) * 128))[j2]);
        }
        crw[r * 65 + j2] = make_ulonglong2(S, L);
    }
    __syncthreads();

    float* hbc = g_h + (size_t)bc * Fh * AW + a0 * Wd + c0;
    const ull* b2p = (const ull*)b2f;
    const ull N1 = NEG1P;

    double totg[8];
    float rmax[32];
    ull sqacc[16];
    if (!LAST) {
#pragma unroll
        for (int k = 0; k < 8; k++) totg[k] = 0.0;
#pragma unroll
        for (int f = 0; f < 32; f++) rmax[f] = -FLT_MAX;
    } else {
#pragma unroll
        for (int f2 = 0; f2 < 16; f2++) sqacc[f2] = 0ull;
    }

    for (int it = 0; it < 2; ++it) {
        int pl = it * STPB + tid;        // 0..511
        int al = pl >> 5, wl = pl & 31;  // warp = one row
        int p = al * Wd + wl;            // offset within (a0,c0) window
        bool valid = (a0 + al < rl) && (c0 + wl < cl);
        if (!__any_sync(0xffffffffu, valid)) continue;

        float hf[32];
#pragma unroll
        for (int f = 0; f < 32; f++) hf[f] = hbc[(size_t)f * AW + p];

        ull e0d[8];
#pragma unroll
        for (int k = 0; k < 8; k++) e0d[k] = dup2(sin_acc(hf[4 * k]));
        // o init: exact TwoSum(h, b2)  (skip + b2)
        ull oS[16], oL[16];
#pragma unroll
        for (int f2 = 0; f2 < 16; f2++) {
            ull hp2 = mk2(hf[2 * f2], hf[2 * f2 + 1]);
            ull bv = b2p[f2];
            ull s1 = add2(hp2, bv);
            ull ap = fma2(bv, N1, s1);
            ull bp = fma2(ap, N1, s1);
            ull ea = fma2(ap, N1, hp2);
            ull eb = fma2(bp, N1, bv);
            oS[f2] = s1;
            oL[f2] = add2(ea, eb);
        }

        const ulonglong2* crp = crw + al * 65;
        const ulonglong2* ctp = ctw + wl * 65;

#pragma unroll 1
        for (int j2 = 0; j2 < 64; j2++) {
            ulonglong2 cr = crp[j2];
            ulonglong2 ct = ctp[j2];
            ull S = cr.x, L = cr.y;
            df_add(S, L, ct.x, ct.y);
            // L1 e0 terms: plain packed fp32 accumulator, weights via 4x LDS.128
            const ulonglong2* we = (const ulonglong2*)(w1e0 + j2 * 8);
            ulonglong2 wv0 = we[0], wv1 = we[1], wv2 = we[2], wv3 = we[3];
            ull acc = mul2(e0d[0], wv0.x);
            acc = fma2(e0d[1], wv0.y, acc);
            acc = fma2(e0d[2], wv1.x, acc);
            acc = fma2(e0d[3], wv1.y, acc);
            acc = fma2(e0d[4], wv2.x, acc);
            acc = fma2(e0d[5], wv2.y, acc);
            acc = fma2(e0d[6], wv3.x, acc);
            acc = fma2(e0d[7], wv3.y, acc);
            // Knuth merge of acc into (S,L)
            {
                ull s1 = add2(S, acc);
                ull ap = fma2(acc, N1, s1);
                ull bp = fma2(ap, N1, s1);
                ull ea = fma2(ap, N1, S);
                ull eb = fma2(bp, N1, acc);
                ull er = add2(ea, eb);
                L = add2(L, er);
                S = s1;
            }
            ull rsum = add2(S, L);
            ull tz = fma2(rsum, N1, S);
            ull rlo = add2(tz, L);
            float rh0 = lof(rsum), rh1 = hif(rsum);
            float rl0 = lof(rlo),  rl1 = hif(rlo);
            if (rh0 + rl0 <= 0.f) { rh0 = 0.f; rl0 = 0.f; }
            if (rh1 + rl1 <= 0.f) { rh1 = 0.f; rl1 = 0.f; }
            {
                ull rhd = dup2(rh0), rld = dup2(rl0);
                const ulonglong2* wr2 = (const ulonglong2*)(w2s + (2 * j2) * 32);
#pragma unroll
                for (int q = 0; q < 8; q++) {
                    ulonglong2 wv = wr2[q];
                    df_macf(oS[2 * q],     oL[2 * q],     rhd, rld, wv.x);
                    df_macf(oS[2 * q + 1], oL[2 * q + 1], rhd, rld, wv.y);
                }
            }
            {
                ull rhd = dup2(rh1), rld = dup2(rl1);
                const ulonglong2* wr2 = (const ulonglong2*)(w2s + (2 * j2 + 1) * 32);
#pragma unroll
                for (int q = 0; q < 8; q++) {
                    ulonglong2 wv = wr2[q];
                    df_macf(oS[2 * q],     oL[2 * q],     rhd, rld, wv.x);
                    df_macf(oS[2 * q + 1], oL[2 * q + 1], rhd, rld, wv.y);
                }
            }
        }
        ull vv[16];
#pragma unroll
        for (int f2 = 0; f2 < 16; f2++) {
            ull v = add2(oS[f2], oL[f2]);
            vv[f2] = valid ? v : 0ull;
        }
        if (!LAST) {
#pragma unroll
            for (int f2 = 0; f2 < 16; f2++) {
                hbc[(size_t)(2 * f2) * AW + p]     = lof(vv[f2]);
                hbc[(size_t)(2 * f2 + 1) * AW + p] = hif(vv[f2]);
            }
#pragma unroll
            for (int k = 0; k < 8; k++) {
                float y1 = sin_acc(hif(vv[2 * k]));
                float y2 = sin_acc(lof(vv[2 * k + 1]));
                float y3 = sin_acc(hif(vv[2 * k + 1]));
                totg[k] += (double)y3;
                atomicAdd(&s_ecol[k * 32 + wl], (double)y2);
                double srw = warpsumd((double)y1);
                if (lane == 0) atomicAdd(&s_erow[al * 8 + k], srw);
            }
#pragma unroll
            for (int f2 = 0; f2 < 16; f2++) {
                rmax[2 * f2]     = fmaxf(rmax[2 * f2],     lof(vv[f2]));
                rmax[2 * f2 + 1] = fmaxf(rmax[2 * f2 + 1], hif(vv[f2]));
            }
        } else {
#pragma unroll
            for (int f2 = 0; f2 < 16; f2++) sqacc[f2] = fma2(vv[f2], vv[f2], sqacc[f2]);
        }
    }
    if (!LAST) {
#pragma unroll
        for (int k = 0; k < 8; k++) {
            double s = warpsumd(totg[k]);
            if (lane == 0) atomicAdd(&s_etot[k], s);
        }
#pragma unroll
        for (int f = 0; f < 32; f++) {
            float m = warpmaxf(rmax[f]);
            if (lane == 0) atomicMax(&s_emax[f], encf(m));
        }
        __syncthreads();
        for (int e = tid; e < 128; e += STPB)
            atomicAdd(&g_rowsum[wi * SETR + bc * 768 + a0 * 8 + e], s_erow[e]);
        for (int e = tid; e < 256; e += STPB) {
            int wl2 = e >> 3, kk = e & 7;
            atomicAdd(&g_colsum[wi * SETC + bc * 768 + (c0 + wl2) * 8 + kk], s_ecol[kk * 32 + wl2]);
        }
        if (tid < 8) atomicAdd(&g_tot[wi * SETT + bc * 8 + tid], s_etot[tid]);
        if (tid < 32) atomicMax(&g_hmax[wi * SETM + bc * 32 + tid], s_emax[tid]);
    } else {
#pragma unroll
        for (int f2 = 0; f2 < 16; f2++) {
            double slo = warpsumd((double)lof(sqacc[f2]));
            double shi = warpsumd((double)hif(sqacc[f2]));
            if (lane == 0) {
                atomicAdd(&s_erow[2 * f2], slo);
                atomicAdd(&s_erow[2 * f2 + 1], shi);
            }
        }
        __syncthreads();
        if (tid < 32) atomicAdd(&g_sq[bc * 32 + tid], s_erow[tid]);
    }
}

// ---------------- output head (double) ----------------
__global__ void out_kernel(const int* __restrict__ rlp, const int* __restrict__ clp,
                           const float* __restrict__ w1, const float* __restrict__ b1,
                           const float* __restrict__ w2, const float* __restrict__ b2,
                           float* __restrict__ out) {
    int tid = threadIdx.x;
    __shared__ double s_h[Bq][32];
    __shared__ double s_r[128];
    int b = tid >> 5, f = tid & 31;
    double acc = 0.0;
    for (int c = 0; c < Cc; c++) {
        int bc = b * Cc + c;
        double n = (double)(rlp[bc] * clp[bc]);
        double sq = fmax(g_sq[bc * 32 + f], 1e-20);
        acc += sqrt(sq / fmax(n, 1e-12));
    }
    s_h[b][f] = acc / (double)Cc;
    __syncthreads();
    for (int bb = 0; bb < Bq; bb++) {
        if (tid < 128) {
            double r = (double)b1[tid];
            for (int ff = 0; ff < 32; ff++) r = fma(s_h[bb][ff], (double)w1[ff * 128 + tid], r);
            s_r[tid] = fmax(r, 0.0);
        }
        __syncthreads();
        if (tid < 2) {
            double o = (double)b2[tid];
            for (int j = 0; j < 128; j++) o = fma(s_r[j], (double)w2[j * 2 + tid], o);
            out[bb * 2 + tid] = (float)(8.0 * tanh(o));
        }
        __syncthreads();
    }
}

// ---------------- host ----------------
extern "C" void kernel_launch(void* const* d_in, const int* in_sizes, int n_in,
                              void* d_out, int out_size) {
    (void)in_sizes; (void)n_in; (void)out_size;
    const float* x    = (const float*)d_in[0];
    const int*   rl   = (const int*)d_in[1];
    const int*   cl   = (const int*)d_in[2];
    const float* t0w1 = (const float*)d_in[3];
    const float* t0b1 = (const float*)d_in[4];
    const float* t0w2 = (const float*)d_in[5];
    const float* t0b2 = (const float*)d_in[6];
    const float* tw1  = (const float*)d_in[7];
    const float* tb1  = (const float*)d_in[8];
    const float* tw2  = (const float*)d_in[9];
    const float* tb2  = (const float*)d_in[10];
    const float* ow1  = (const float*)d_in[11];
    const float* ob1  = (const float*)d_in[12];
    const float* ow2  = (const float*)d_in[13];
    const float* ob2  = (const float*)d_in[14];

    cudaFuncSetAttribute(stack_kernel<false>, cudaFuncAttributeMaxDynamicSharedMemorySize, STACK_SMEM);
    cudaFuncSetAttribute(stack_kernel<true>,  cudaFuncAttributeMaxDynamicSharedMemorySize, STACK_SMEM);
    cudaFuncSetAttribute(mlp0_eval, cudaFuncAttributeMaxDynamicSharedMemorySize, EV_SMEM);

    const int SGRID = BCn * 18;   // 192 bc x 6 row-chunks x 3 col-chunks

    stats_kernel<<<BCn, 256>>>(x, rl, cl);
    mlp0_pre<<<1, 128>>>(t0w1, t0b1, t0w2, t0b2);
    zero_set<<<576, 256>>>(0);
    zero_set<<<576, 256>>>(1);
    mlp0_eval<<<BCn * CHUNKS, MTPB, EV_SMEM>>>(x, rl, cl);   // writes set 0

    // stack i reads set (i&1), writes set 1-(i&1)
    stack_kernel<false><<<SGRID, STPB, STACK_SMEM>>>(
        tw1, tb1, tw2, tb2, rl, cl, 0);
    zero_set<<<576, 256>>>(0);
    stack_kernel<false><<<SGRID, STPB, STACK_SMEM>>>(
        tw1 + 8192, tb1 + 128, tw2 + 4096, tb2 + 32, rl, cl, 1);
    zero_set<<<576, 256>>>(1);
    stack_kernel<false><<<SGRID, STPB, STACK_SMEM>>>(
        tw1 + 2 * 8192, tb1 + 2 * 128, tw2 + 2 * 4096, tb2 + 2 * 32, rl, cl, 0);
    stack_kernel<true><<<SGRID, STPB, STACK_SMEM>>>(
        tw1 + 3 * 8192, tb1 + 3 * 128, tw2 + 3 * 4096, tb2 + 3 * 32, rl, cl, 1);

    out_kernel<<<1, 256>>>(rl, cl, ow1, ob1, ow2, ob2, (float*)d_out);
}

// round 16
// speedup vs baseline: 1.0126x; 1.0126x over previous
#include <cuda_runtime.h>
#include <math.h>
#include <float.h>

typedef unsigned long long ull;

#define Ad 96
#define Wd 96
#define Cc 24
#define Bq 8
#define BCn 192
#define AW 9216
#define CHUNKS 6
#define CROWS 16
#define Fh 32

#define STPB 384
#define MTPB 384

#define SETR (BCn * 768)
#define SETC (BCn * 768)
#define SETT (BCn * 8)
#define SETM (BCn * 32)

// ---------------- device scratch ----------------
__device__ float    g_h[(size_t)BCn * Fh * AW];   // h: [bc][f][pos] fp32
__device__ double   g_rowsum[2 * SETR];
__device__ double   g_colsum[2 * SETC];
__device__ double   g_tot[2 * SETT];
__device__ unsigned g_hmax[2 * SETM];             // encoded-uint max
__device__ double   g_sq[BCn * Fh];
__device__ double   g_mean[BCn];
__device__ double   g_istd[BCn];
// PWL tables for mlp0: 129 segments
__device__ double g_tsort[128];
__device__ double g_A[129][32];
__device__ double g_B[129][32];

// ---------------- packed fp32 helpers (asm: fast-math-proof) ----------------
#define NEG1P 0xBF800000BF800000ULL   /* {-1.0f, -1.0f} */
#define SGN2  0x8000000080000000ULL

__device__ __forceinline__ float lof(ull v) { return __uint_as_float((unsigned)v); }
__device__ __forceinline__ float hif(ull v) { return __uint_as_float((unsigned)(v >> 32)); }
__device__ __forceinline__ ull dup2(float x) { ull r; asm("mov.b64 %0,{%1,%1};" : "=l"(r) : "f"(x)); return r; }
__device__ __forceinline__ ull mk2(float x, float y) { ull r; asm("mov.b64 %0,{%1,%2};" : "=l"(r) : "f"(x), "f"(y)); return r; }
__device__ __forceinline__ ull neg2(ull a) { return a ^ SGN2; }
__device__ __forceinline__ ull mul2(ull a, ull b) {
    ull d; asm("mul.rn.f32x2 %0,%1,%2;" : "=l"(d) : "l"(a), "l"(b)); return d;
}
__device__ __forceinline__ ull add2(ull a, ull b) {
    ull d; asm("add.rn.f32x2 %0,%1,%2;" : "=l"(d) : "l"(a), "l"(b)); return d;
}
__device__ __forceinline__ ull fma2(ull a, ull b, ull c) {
    ull d; asm("fma.rn.f32x2 %0,%1,%2,%3;" : "=l"(d) : "l"(a), "l"(b), "l"(c)); return d;
}

// df MAC, Knuth TwoSum (exact; precompute paths)
__device__ __forceinline__ void df_mac(ull& S, ull& L, ull rh, ull rl, ull w) {
    const ull N1 = NEG1P;
    ull p  = mul2(rh, w);
    ull e  = fma2(rh, w, neg2(p));
    e      = fma2(rl, w, e);
    ull s1 = add2(S, p);
    ull ap = fma2(p, N1, s1);
    ull bp = fma2(ap, N1, s1);
    ull ea = fma2(ap, N1, S);
    ull eb = fma2(bp, N1, p);
    ull er = add2(ea, eb);
    L      = add2(L, er);
    L      = add2(L, e);
    S      = s1;
}
// df MAC, Fast2Sum compensation (8 ops; inner-loop L2).
// EXACT TwoProd residual is load-bearing (R12 post-mortem);
// only the addition compensation is approximate (loss when |p|>|S|: rare).
__device__ __forceinline__ void df_macf(ull& S, ull& L, ull rh, ull rl, ull w) {
    const ull N1 = NEG1P;
    ull p  = mul2(rh, w);
    ull e  = fma2(rh, w, neg2(p));
    e      = fma2(rl, w, e);
    ull s1 = add2(S, p);
    ull z  = fma2(S, N1, s1);    // s1 - S
    ull e2 = fma2(z, N1, p);     // p - z
    L      = add2(L, e2);
    L      = add2(L, e);
    S      = s1;
}
// (S,L) += (bh, bl) df + df, Knuth (exact)
__device__ __forceinline__ void df_add(ull& S, ull& L, ull bh, ull bl) {
    const ull N1 = NEG1P;
    ull s1 = add2(S, bh);
    ull ap = fma2(bh, N1, s1);
    ull bp = fma2(ap, N1, s1);
    ull ea = fma2(ap, N1, S);
    ull eb = fma2(bp, N1, bh);
    ull er = add2(ea, eb);
    L      = add2(L, bl);
    L      = add2(L, er);
    S      = s1;
}

__device__ __forceinline__ unsigned encf(float x) {
    int i = __float_as_int(x);
    return (i >= 0) ? ((unsigned)i | 0x80000000u) : ~(unsigned)i;
}
__device__ __forceinline__ float decf(unsigned u) {
    int i = (u & 0x80000000u) ? (int)(u & 0x7fffffffu) : ~(int)u;
    return __int_as_float(i);
}
#define ENC_NEGMAX 0x00800000u
#define ENC_ZERO   0x80000000u

__device__ __forceinline__ double warpsumd(double v) {
    v += __shfl_xor_sync(0xffffffffu, v, 16);
    v += __shfl_xor_sync(0xffffffffu, v, 8);
    v += __shfl_xor_sync(0xffffffffu, v, 4);
    v += __shfl_xor_sync(0xffffffffu, v, 2);
    v += __shfl_xor_sync(0xffffffffu, v, 1);
    return v;
}
__device__ __forceinline__ float warpmaxf(float v) {
    v = fmaxf(v, __shfl_xor_sync(0xffffffffu, v, 16));
    v = fmaxf(v, __shfl_xor_sync(0xffffffffu, v, 8));
    v = fmaxf(v, __shfl_xor_sync(0xffffffffu, v, 4));
    v = fmaxf(v, __shfl_xor_sync(0xffffffffu, v, 2));
    v = fmaxf(v, __shfl_xor_sync(0xffffffffu, v, 1));
    return v;
}

// Accurate fp32 sin (1-2 ulp), fast-math-proof.
__device__ __forceinline__ float sin_acc(float x) {
    float n = rintf(x * 0.318309886183790672f);
    float r = fmaf(n, -3.140625f, x);
    r = fmaf(n, -9.67502593994140625e-4f, r);
    r = fmaf(n, -1.50995799097837643e-7f, r);
    float r2 = r * r;
    float p = fmaf(r2, 2.60831598e-06f, -1.98106907e-04f);
    p = fmaf(r2, p, 8.33330786e-03f);
    p = fmaf(r2, p, -1.66666597e-01f);
    float s = fmaf(r * r2, p, r);
    int ni = (int)n;
    return __int_as_float(__float_as_int(s) ^ ((ni & 1) << 31));
}
// Packed pair sin: lane-wise IDENTICAL RN ops to sin_acc (bit-identical results).
__device__ __forceinline__ ull sin_acc2(float x0, float x1) {
    float n0 = rintf(x0 * 0.318309886183790672f);
    float n1 = rintf(x1 * 0.318309886183790672f);
    ull xv = mk2(x0, x1);
    ull nv = mk2(n0, n1);
    ull r = fma2(nv, dup2(-3.140625f), xv);
    r = fma2(nv, dup2(-9.67502593994140625e-4f), r);
    r = fma2(nv, dup2(-1.50995799097837643e-7f), r);
    ull r2 = mul2(r, r);
    ull p = fma2(r2, dup2(2.60831598e-06f), dup2(-1.98106907e-04f));
    p = fma2(r2, p, dup2(8.33330786e-03f));
    p = fma2(r2, p, dup2(-1.66666597e-01f));
    ull s = fma2(mul2(r, r2), p, r);
    unsigned m0 = ((unsigned)((int)n0 & 1)) << 31;
    unsigned m1 = ((unsigned)((int)n1 & 1)) << 31;
    return s ^ (((ull)m1 << 32) | (ull)m0);
}

// ---------------- per-matrix mean / inv-std + g_sq zero ----------------
__global__ void stats_kernel(const float* __restrict__ x,
                             const int* __restrict__ rlp, const int* __restrict__ clp) {
    int bc = blockIdx.x, tid = threadIdx.x;
    int rl = rlp[bc], cl = clp[bc];
    double s = 0.0, s2 = 0.0;
    const float* xp = x + (size_t)bc * AW;
    for (int p = tid; p < AW; p += 256) {
        int a = p / Wd, w = p - a * Wd;
        if (a < rl && w < cl) { double v = (double)xp[p]; s += v; s2 += v * v; }
    }
    __shared__ double sh[256], sh2[256];
    sh[tid] = s; sh2[tid] = s2;
    __syncthreads();
    for (int o = 128; o; o >>= 1) {
        if (tid < o) { sh[tid] += sh[tid + o]; sh2[tid] += sh2[tid + o]; }
        __syncthreads();
    }
    if (tid == 0) {
        double n = (double)rl * (double)cl;
        double mean = sh[0] / n;
        double var = (sh2[0] - n * mean * mean) / (n - 1.0);
        g_mean[bc] = mean;
        g_istd[bc] = 1.0 / fmax(sqrt(fmax(var, 0.0)), 1e-12);
    }
    if (tid < 32) g_sq[bc * 32 + tid] = 0.0;
}

// ---------------- zero one accumulator set ----------------
__global__ void zero_set(int s) {
    int i = blockIdx.x * 256 + threadIdx.x;   // 576*256 = SETC
    g_colsum[s * SETC + i] = 0.0;
    if (i < SETT) g_tot[s * SETT + i] = 0.0;
    if (i < SETM) g_hmax[s * SETM + i] = ENC_NEGMAX;
}

// ---------------- mlp0 PWL precompute ----------------
__global__ void mlp0_pre(const float* __restrict__ w01, const float* __restrict__ b01,
                         const float* __restrict__ w2, const float* __restrict__ b2) {
    __shared__ double tval[128];
    __shared__ int order[128];
    __shared__ double tsort[128];
    int j = threadIdx.x;   // 128 threads
    double wj = (double)w01[j], bj = (double)b01[j];
    double t = (wj != 0.0) ? (-bj / wj) : DBL_MAX;
    tval[j] = t;
    __syncthreads();
    int rank = 0;
    for (int k = 0; k < 128; k++) {
        double tk = tval[k];
        rank += (tk < t) || (tk == t && k < j);
    }
    order[rank] = j;
    tsort[rank] = t;
    __syncthreads();
    g_tsort[j] = tsort[j];
    if (j < 32) {
        int f = j;
        double A = 0.0, B = (double)b2[f];
        for (int k = 0; k < 128; k++) {
            double wk = (double)w01[k], bk = (double)b01[k];
            if (wk < 0.0 || (wk == 0.0 && bk > 0.0)) {
                double w2v = (double)w2[k * 32 + f];
                A += wk * w2v; B += bk * w2v;
            }
        }
        g_A[0][f] = A; g_B[0][f] = B;
        for (int s = 1; s <= 128; s++) {
            int k = order[s - 1];
            double wk = (double)w01[k], bk = (double)b01[k];
            double w2v = (double)w2[k * 32 + f];
            if (wk > 0.0)      { A += wk * w2v; B += bk * w2v; }
            else if (wk < 0.0) { A -= wk * w2v; B -= bk * w2v; }
            g_A[s][f] = A; g_B[s][f] = B;
        }
    }
}

// ---------------- mlp0 eval: PWL + fused stack-0 reduction epilogue (writes set 0) ----------------
#define EVD_PWL (128 + 2 * 129 * 33)
#define EVD_ROW EVD_PWL
#define EVD_COL (EVD_ROW + 128)
#define EVD_TOT (EVD_COL + 768)
#define EVD_MAX (EVD_TOT + 8)
#define EV_SMEM ((EVD_MAX + 16) * 8)
__global__ void __launch_bounds__(MTPB, 1)
mlp0_eval(const float* __restrict__ x,
          const int* __restrict__ rlp, const int* __restrict__ clp) {
    int bid = blockIdx.x;
    int bc = bid / CHUNKS, chunk = bid - (bid / CHUNKS) * CHUNKS;
    int a0 = chunk * CROWS;
    int tid = threadIdx.x, lane = tid & 31;
    int rl = rlp[bc], cl = clp[bc];
    if (a0 >= rl) {
        if (tid < 32) atomicMax(&g_hmax[bc * 32 + tid], ENC_ZERO);
        return;
    }
    extern __shared__ double smd[];
    double* s_t = smd;
    double* s_A = smd + 128;
    double* s_B = s_A + 129 * 33;
    double*   s_erow = smd + EVD_ROW;
    double*   s_ecol = smd + EVD_COL;
    double*   s_etot = smd + EVD_TOT;
    unsigned* s_emax = (unsigned*)(smd + EVD_MAX);
    bool hasInv = (rl < a0 + CROWS) || (cl < Wd);
    for (int e = tid; e < 129 * 32; e += MTPB) {
        int s = e >> 5, f = e & 31;
        s_A[s * 33 + f] = g_A[s][f];
        s_B[s * 33 + f] = g_B[s][f];
    }
    if (tid < 128) s_t[tid] = g_tsort[tid];
    for (int e = tid; e < 128; e += MTPB) s_erow[e] = 0.0;
    for (int e = tid; e < 768; e += MTPB) s_ecol[e] = 0.0;
    if (tid < 8) s_etot[tid] = 0.0;
    if (tid < 32) s_emax[tid] = hasInv ? ENC_ZERO : ENC_NEGMAX;
    __syncthreads();

    double meand = g_mean[bc], istdd = g_istd[bc];
    const float* xp = x + (size_t)bc * AW + a0 * Wd;
    float* hbc = g_h + (size_t)bc * Fh * AW + a0 * Wd;

    double totg[8];
    float rmax[32];
#pragma unroll
    for (int k = 0; k < 8; k++) totg[k] = 0.0;
#pragma unroll
    for (int f = 0; f < 32; f++) rmax[f] = -FLT_MAX;

    for (int it = 0; it < 4; ++it) {
        int p = it * MTPB + tid;
        int al = p / Wd, w = p - al * Wd;
        bool valid = (a0 + al < rl) && (w < cl);
        if (!__any_sync(0xffffffffu, valid)) continue;
        float xnf = valid ? (float)(((double)xp[p] - meand) * istdd) : 0.f;
        double xd = (double)xnf;
        int lo = 0, hi = 128;
#pragma unroll
        for (int st = 0; st < 7; st++) {
            int mid = (lo + hi) >> 1;
            bool c = s_t[mid] < xd;
            lo = c ? mid + 1 : lo;
            hi = c ? hi : mid;
        }
        const double* Ar = s_A + lo * 33;
        const double* Br = s_B + lo * 33;
        float hv[32];
#pragma unroll
        for (int f = 0; f < 32; f++) {
            double o = fma(Ar[f], xd, Br[f]);
            hv[f] = valid ? (float)o : 0.f;
            hbc[(size_t)f * AW + p] = hv[f];
        }
#pragma unroll
        for (int k = 0; k < 8; k++) {
            ull y12 = sin_acc2(hv[4 * k + 1], hv[4 * k + 2]);
            float y1 = lof(y12), y2 = hif(y12);
            float y3 = sin_acc(hv[4 * k + 3]);
            totg[k] += (double)y3;
            atomicAdd(&s_ecol[k * 96 + w], (double)y2);
            double srw = warpsumd((double)y1);
            if (lane == 0) atomicAdd(&s_erow[al * 8 + k], srw);
        }
#pragma unroll
        for (int f = 0; f < 32; f++) rmax[f] = fmaxf(rmax[f], hv[f]);
    }
#pragma unroll
    for (int k = 0; k < 8; k++) {
        double s = warpsumd(totg[k]);
        if (lane == 0) atomicAdd(&s_etot[k], s);
    }
#pragma unroll
    for (int f = 0; f < 32; f++) {
        float m = warpmaxf(rmax[f]);
        if (lane == 0) atomicMax(&s_emax[f], encf(m));
    }
    __syncthreads();
    for (int e = tid; e < 128; e += MTPB) g_rowsum[bc * 768 + a0 * 8 + e] = s_erow[e];
    for (int e = tid; e < 768; e += MTPB) {
        int wi2 = e >> 3, kk = e & 7;
        atomicAdd(&g_colsum[bc * 768 + e], s_ecol[kk * 96 + wi2]);
    }
    if (tid < 8) atomicAdd(&g_tot[bc * 8 + tid], s_etot[tid]);
    if (tid < 32) atomicMax(&g_hmax[bc * 32 + tid], s_emax[tid]);
}

// ---------------- one equivariant stack (df, R14 shape) + fused epilogue ----------------
#define SK_W1   0        /* 8192 */
#define SK_W2   8192     /* 4096 */
#define SK_CROW 12288    /* 16*65 ull2 = 4160 floats */
#define SK_COLT 16448    /* 96*65 ull2 = 24960 floats */
#define SK_CSD  41408    /* float2 x768 = 1536 */
#define SK_RSD  42944    /* float2 x128 = 256 */
#define SK_BASE 43200    /* double x128 = 256 */
#define SK_TT   43456    /* double x8 = 16 */
#define SK_HM   43472    /* 32 */
#define SK_B1   43504    /* 128 */
#define SK_B2   43632    /* 32 */
#define SE_ROW  43664    /* double x128 = 256 */
#define SE_COL  43920    /* double x768 = 1536 */
#define SE_TOT  45456    /* double x8 = 16 */
#define SE_MAX  45472    /* 32 u32 */
#define SK_W1E0 45504    /* 64*8 ull = 1024 floats */
#define SK_TOTF 46528
#define STACK_SMEM (SK_TOTF * 4)

template <bool LAST>
__global__ void __launch_bounds__(STPB, 1)
stack_kernel(const float* __restrict__ w1g, const float* __restrict__ b1g,
             const float* __restrict__ w2g, const float* __restrict__ b2g,
             const int* __restrict__ rlp, const int* __restrict__ clp, int ri) {
    int bid = blockIdx.x;
    int bc = bid / CHUNKS, chunk = bid - (bid / CHUNKS) * CHUNKS;
    int a0 = chunk * CROWS;
    int tid = threadIdx.x, lane = tid & 31;
    int rl = rlp[bc], cl = clp[bc];
    int wi = 1 - ri;
    if (a0 >= rl) {
        if (!LAST && tid < 32) atomicMax(&g_hmax[wi * SETM + bc * 32 + tid], ENC_ZERO);
        return;
    }
    int b = bc / Cc;

    extern __shared__ float smf[];
    float*      w1s  = smf + SK_W1;
    float*      w2s  = smf + SK_W2;
    ulonglong2* crw  = (ulonglong2*)(smf + SK_CROW);
    ulonglong2* ctw  = (ulonglong2*)(smf + SK_COLT);
    float2*     csd  = (float2*)(smf + SK_CSD);
    float2*     rsd  = (float2*)(smf + SK_RSD);
    double*     based= (double*)(smf + SK_BASE);
    double*     ttd  = (double*)(smf + SK_TT);
    float*      hmf  = smf + SK_HM;
    float*      b1f  = smf + SK_B1;
    float*      b2f  = smf + SK_B2;
    double*     s_erow = (double*)(smf + SE_ROW);
    double*     s_ecol = (double*)(smf + SE_COL);
    double*     s_etot = (double*)(smf + SE_TOT);
    unsigned*   s_emax = (unsigned*)(smf + SE_MAX);
    ull*        w1e0 = (ull*)(smf + SK_W1E0);   // [j2][k]
    bool hasInv = (rl < a0 + CROWS) || (cl < Wd);

    for (int e = tid; e < 8192; e += STPB) w1s[e] = w1g[e];
    for (int e = tid; e < 4096; e += STPB) w2s[e] = w2g[e];
    if (tid < 128) b1f[tid] = b1g[tid];
    if (tid < 32)  b2f[tid] = b2g[tid];
    for (int e = tid; e < 768; e += STPB) {
        double v = g_colsum[ri * SETC + bc * 768 + e];
        float hi = (float)v;
        csd[e] = make_float2(hi, (float)(v - (double)hi));
    }
    if (tid < 128) {
        double v = g_rowsum[ri * SETR + bc * 768 + a0 * 8 + tid];
        float hi = (float)v;
        rsd[tid] = make_float2(hi, (float)(v - (double)hi));
    }
    if (tid < 8) ttd[tid] = g_tot[ri * SETT + bc * 8 + tid];
    if (tid < 32) {
        float m = -FLT_MAX;
        for (int c = 0; c < Cc; c++) m = fmaxf(m, decf(g_hmax[ri * SETM + (b * Cc + c) * 32 + tid]));
        hmf[tid] = m;
    }
    if (!LAST) {
        for (int e = tid; e < 128; e += STPB) s_erow[e] = 0.0;
        for (int e = tid; e < 768; e += STPB) s_ecol[e] = 0.0;
        if (tid < 8) s_etot[tid] = 0.0;
        if (tid < 32) s_emax[tid] = hasInv ? ENC_ZERO : ENC_NEGMAX;
    } else {
        if (tid < 32) s_erow[tid] = 0.0;   // reused as s_sq
    }
    __syncthreads();
    if (tid < 128) {   // base[j] = b1 + tot-term + max-term (fp64)
        double acc = (double)b1f[tid];
#pragma unroll
        for (int k = 0; k < 8; k++) acc = fma(ttd[k], (double)w1s[(24 + k) * 128 + tid], acc);
#pragma unroll
        for (int f = 0; f < 32; f++) acc = fma((double)hmf[f], (double)w1s[(32 + f) * 128 + tid], acc);
        based[tid] = acc;
    }
    // repack w1 e0 rows: w1e0[j2*8 + k] = {w1[k][2j2], w1[k][2j2+1]}
    for (int e = tid; e < 512; e += STPB) {
        int j2 = e >> 3, k = e & 7;
        w1e0[e] = ((const ull*)(w1s + k * 128))[j2];
    }
    __syncthreads();
    // colt df: [w][j] = sum_k cs_df[w][k] * w1[16+k][j] (exact Knuth)
    for (int e = tid; e < 6144; e += STPB) {
        int w = e >> 6, j2 = e & 63;
        ull S = 0ull, L = 0ull;
#pragma unroll
        for (int k = 0; k < 8; k++) {
            float2 c = csd[w * 8 + k];
            df_mac(S, L, dup2(c.x), dup2(c.y), ((const ull*)(w1s + (16 + k) * 128))[j2]);
        }
        ctw[w * 65 + j2] = make_ulonglong2(S, L);
    }
    // crow df: [r][j] = base + sum_k rs_df[r][k] * w1[8+k][j] (exact Knuth)
    for (int e = tid; e < 1024; e += STPB) {
        int r = e >> 6, j2 = e & 63;
        double b0 = based[2 * j2], b1v = based[2 * j2 + 1];
        float bh0 = (float)b0, bh1 = (float)b1v;
        ull S = mk2(bh0, bh1);
        ull L = mk2((float)(b0 - (double)bh0), (float)(b1v - (double)bh1));
#pragma unroll
        for (int k = 0; k < 8; k++) {
            float2 rr = rsd[r * 8 + k];
            df_mac(S, L, dup2(rr.x), dup2(rr.y), ((const ull*)(w1s + (8 + k) * 128))[j2]);
        }
        crw[r * 65 + j2] = make_ulonglong2(S, L);
    }
    __syncthreads();

    float* hbc = g_h + (size_t)bc * Fh * AW + a0 * Wd;
    const ull* b2p = (const ull*)b2f;
    const ull N1 = NEG1P;

    double totg[8];
    float rmax[32];
    ull sqacc[16];
    if (!LAST) {
#pragma unroll
        for (int k = 0; k < 8; k++) totg[k] = 0.0;
#pragma unroll
        for (int f = 0; f < 32; f++) rmax[f] = -FLT_MAX;
    } else {
#pragma unroll
        for (int f2 = 0; f2 < 16; f2++) sqacc[f2] = 0ull;
    }

    for (int it = 0; it < 4; ++it) {
        int p = it * STPB + tid;
        int al = p / Wd, w = p - al * Wd;
        bool valid = (a0 + al < rl) && (w < cl);
        if (!__any_sync(0xffffffffu, valid)) continue;

        float hf[32];
#pragma unroll
        for (int f = 0; f < 32; f++) hf[f] = hbc[(size_t)f * AW + p];

        ull e0d[8];
#pragma unroll
        for (int kk2 = 0; kk2 < 4; kk2++) {   // packed sin pairs (bit-identical per lane)
            ull sp = sin_acc2(hf[8 * kk2], hf[8 * kk2 + 4]);
            e0d[2 * kk2]     = dup2(lof(sp));
            e0d[2 * kk2 + 1] = dup2(hif(sp));
        }
        // o init: exact TwoSum(h, b2)  (skip + b2)
        ull oS[16], oL[16];
#pragma unroll
        for (int f2 = 0; f2 < 16; f2++) {
            ull hp2 = mk2(hf[2 * f2], hf[2 * f2 + 1]);
            ull bv = b2p[f2];
            ull s1 = add2(hp2, bv);
            ull ap = fma2(bv, N1, s1);
            ull bp = fma2(ap, N1, s1);
            ull ea = fma2(ap, N1, hp2);
            ull eb = fma2(bp, N1, bv);
            oS[f2] = s1;
            oL[f2] = add2(ea, eb);
        }

        const ulonglong2* crp = crw + al * 65;
        const ulonglong2* ctp = ctw + w * 65;

#pragma unroll 2
        for (int j2 = 0; j2 < 64; j2++) {
            ulonglong2 cr = crp[j2];
            ulonglong2 ct = ctp[j2];
            ull S = cr.x, L = cr.y;
            df_add(S, L, ct.x, ct.y);
            // L1 e0 terms: plain packed fp32 accumulator, weights via 4x LDS.128
            const ulonglong2* we = (const ulonglong2*)(w1e0 + j2 * 8);
            ulonglong2 wv0 = we[0], wv1 = we[1], wv2 = we[2], wv3 = we[3];
            ull acc = mul2(e0d[0], wv0.x);
            acc = fma2(e0d[1], wv0.y, acc);
            acc = fma2(e0d[2], wv1.x, acc);
            acc = fma2(e0d[3], wv1.y, acc);
            acc = fma2(e0d[4], wv2.x, acc);
            acc = fma2(e0d[5], wv2.y, acc);
            acc = fma2(e0d[6], wv3.x, acc);
            acc = fma2(e0d[7], wv3.y, acc);
            // Knuth merge of acc into (S,L)
            {
                ull s1 = add2(S, acc);
                ull ap = fma2(acc, N1, s1);
                ull bp = fma2(ap, N1, s1);
                ull ea = fma2(ap, N1, S);
                ull eb = fma2(bp, N1, acc);
                ull er = add2(ea, eb);
                L = add2(L, er);
                S = s1;
            }
            ull rsum = add2(S, L);
            ull tz = fma2(rsum, N1, S);
            ull rlo = add2(tz, L);
            float rh0 = lof(rsum), rh1 = hif(rsum);
            float rl0 = lof(rlo),  rl1 = hif(rlo);
            if (rh0 + rl0 <= 0.f) { rh0 = 0.f; rl0 = 0.f; }
            if (rh1 + rl1 <= 0.f) { rh1 = 0.f; rl1 = 0.f; }
            {
                ull rhd = dup2(rh0), rld = dup2(rl0);
                const ulonglong2* wr2 = (const ulonglong2*)(w2s + (2 * j2) * 32);
#pragma unroll
                for (int q = 0; q < 8; q++) {
                    ulonglong2 wv = wr2[q];
                    df_macf(oS[2 * q],     oL[2 * q],     rhd, rld, wv.x);
                    df_macf(oS[2 * q + 1], oL[2 * q + 1], rhd, rld, wv.y);
                }
            }
            {
                ull rhd = dup2(rh1), rld = dup2(rl1);
                const ulonglong2* wr2 = (const ulonglong2*)(w2s + (2 * j2 + 1) * 32);
#pragma unroll
                for (int q = 0; q < 8; q++) {
                    ulonglong2 wv = wr2[q];
                    df_macf(oS[2 * q],     oL[2 * q],     rhd, rld, wv.x);
                    df_macf(oS[2 * q + 1], oL[2 * q + 1], rhd, rld, wv.y);
                }
            }
        }
        ull vv[16];
#pragma unroll
        for (int f2 = 0; f2 < 16; f2++) {
            ull v = add2(oS[f2], oL[f2]);
            vv[f2] = valid ? v : 0ull;
        }
        if (!LAST) {
#pragma unroll
            for (int f2 = 0; f2 < 16; f2++) {
                hbc[(size_t)(2 * f2) * AW + p]     = lof(vv[f2]);
                hbc[(size_t)(2 * f2 + 1) * AW + p] = hif(vv[f2]);
            }
#pragma unroll
            for (int k = 0; k < 8; k++) {
                ull y12 = sin_acc2(hif(vv[2 * k]), lof(vv[2 * k + 1]));
                float y1 = lof(y12), y2 = hif(y12);
                float y3 = sin_acc(hif(vv[2 * k + 1]));
                totg[k] += (double)y3;
                atomicAdd(&s_ecol[k * 96 + w], (double)y2);
                double srw = warpsumd((double)y1);
                if (lane == 0) atomicAdd(&s_erow[al * 8 + k], srw);
            }
#pragma unroll
            for (int f2 = 0; f2 < 16; f2++) {
                rmax[2 * f2]     = fmaxf(rmax[2 * f2],     lof(vv[f2]));
                rmax[2 * f2 + 1] = fmaxf(rmax[2 * f2 + 1], hif(vv[f2]));
            }
        } else {
#pragma unroll
            for (int f2 = 0; f2 < 16; f2++) sqacc[f2] = fma2(vv[f2], vv[f2], sqacc[f2]);
        }
    }
    if (!LAST) {
#pragma unroll
        for (int k = 0; k < 8; k++) {
            double s = warpsumd(totg[k]);
            if (lane == 0) atomicAdd(&s_etot[k], s);
        }
#pragma unroll
        for (int f = 0; f < 32; f++) {
            float m = warpmaxf(rmax[f]);
            if (lane == 0) atomicMax(&s_emax[f], encf(m));
        }
        __syncthreads();
        for (int e = tid; e < 128; e += STPB) g_rowsum[wi * SETR + bc * 768 + a0 * 8 + e] = s_erow[e];
        for (int e = tid; e < 768; e += STPB) {
            int wi2 = e >> 3, kk = e & 7;
            atomicAdd(&g_colsum[wi * SETC + bc * 768 + e], s_ecol[kk * 96 + wi2]);
        }
        if (tid < 8) atomicAdd(&g_tot[wi * SETT + bc * 8 + tid], s_etot[tid]);
        if (tid < 32) atomicMax(&g_hmax[wi * SETM + bc * 32 + tid], s_emax[tid]);
    } else {
#pragma unroll
        for (int f2 = 0; f2 < 16; f2++) {
            double slo = warpsumd((double)lof(sqacc[f2]));
            double shi = warpsumd((double)hif(sqacc[f2]));
            if (lane == 0) {
                atomicAdd(&s_erow[2 * f2], slo);
                atomicAdd(&s_erow[2 * f2 + 1], shi);
            }
        }
        __syncthreads();
        if (tid < 32) atomicAdd(&g_sq[bc * 32 + tid], s_erow[tid]);
    }
}

// ---------------- output head (double) ----------------
__global__ void out_kernel(const int* __restrict__ rlp, const int* __restrict__ clp,
                           const float* __restrict__ w1, const float* __restrict__ b1,
                           const float* __restrict__ w2, const float* __restrict__ b2,
                           float* __restrict__ out) {
    int tid = threadIdx.x;
    __shared__ double s_h[Bq][32];
    __shared__ double s_r[128];
    int b = tid >> 5, f = tid & 31;
    double acc = 0.0;
    for (int c = 0; c < Cc; c++) {
        int bc = b * Cc + c;
        double n = (double)(rlp[bc] * clp[bc]);
        double sq = fmax(g_sq[bc * 32 + f], 1e-20);
        acc += sqrt(sq / fmax(n, 1e-12));
    }
    s_h[b][f] = acc / (double)Cc;
    __syncthreads();
    for (int bb = 0; bb < Bq; bb++) {
        if (tid < 128) {
            double r = (double)b1[tid];
            for (int ff = 0; ff < 32; ff++) r = fma(s_h[bb][ff], (double)w1[ff * 128 + tid], r);
            s_r[tid] = fmax(r, 0.0);
        }
        __syncthreads();
        if (tid < 2) {
            double o = (double)b2[tid];
            for (int j = 0; j < 128; j++) o = fma(s_r[j], (double)w2[j * 2 + tid], o);
            out[bb * 2 + tid] = (float)(8.0 * tanh(o));
        }
        __syncthreads();
    }
}

// ---------------- host ----------------
extern "C" void kernel_launch(void* const* d_in, const int* in_sizes, int n_in,
                              void* d_out, int out_size) {
    (void)in_sizes; (void)n_in; (void)out_size;
    const float* x    = (const float*)d_in[0];
    const int*   rl   = (const int*)d_in[1];
    const int*   cl   = (const int*)d_in[2];
    const float* t0w1 = (const float*)d_in[3];
    const float* t0b1 = (const float*)d_in[4];
    const float* t0w2 = (const float*)d_in[5];
    const float* t0b2 = (const float*)d_in[6];
    const float* tw1  = (const float*)d_in[7];
    const float* tb1  = (const float*)d_in[8];
    const float* tw2  = (const float*)d_in[9];
    const float* tb2  = (const float*)d_in[10];
    const float* ow1  = (const float*)d_in[11];
    const float* ob1  = (const float*)d_in[12];
    const float* ow2  = (const float*)d_in[13];
    const float* ob2  = (const float*)d_in[14];

    cudaFuncSetAttribute(stack_kernel<false>, cudaFuncAttributeMaxDynamicSharedMemorySize, STACK_SMEM);
    cudaFuncSetAttribute(stack_kernel<true>,  cudaFuncAttributeMaxDynamicSharedMemorySize, STACK_SMEM);
    cudaFuncSetAttribute(mlp0_eval, cudaFuncAttributeMaxDynamicSharedMemorySize, EV_SMEM);

    stats_kernel<<<BCn, 256>>>(x, rl, cl);
    mlp0_pre<<<1, 128>>>(t0w1, t0b1, t0w2, t0b2);
    zero_set<<<576, 256>>>(0);
    zero_set<<<576, 256>>>(1);
    mlp0_eval<<<BCn * CHUNKS, MTPB, EV_SMEM>>>(x, rl, cl);   // writes set 0

    // stack i reads set (i&1), writes set 1-(i&1)
    stack_kernel<false><<<BCn * CHUNKS, STPB, STACK_SMEM>>>(
        tw1, tb1, tw2, tb2, rl, cl, 0);
    zero_set<<<576, 256>>>(0);
    stack_kernel<false><<<BCn * CHUNKS, STPB, STACK_SMEM>>>(
        tw1 + 8192, tb1 + 128, tw2 + 4096, tb2 + 32, rl, cl, 1);
    zero_set<<<576, 256>>>(1);
    stack_kernel<false><<<BCn * CHUNKS, STPB, STACK_SMEM>>>(
        tw1 + 2 * 8192, tb1 + 2 * 128, tw2 + 2 * 4096, tb2 + 2 * 32, rl, cl, 0);
    stack_kernel<true><<<BCn * CHUNKS, STPB, STACK_SMEM>>>(
        tw1 + 3 * 8192, tb1 + 3 * 128, tw2 + 3 * 4096, tb2 + 3 * 32, rl, cl, 1);

    out_kernel<<<1, 256>>>(rl, cl, ow1, ob1, ow2, ob2, (float*)d_out);
}

// round 17
// speedup vs baseline: 1.0215x; 1.0088x over previous
#include <cuda_runtime.h>
#include <math.h>
#include <float.h>

typedef unsigned long long ull;

#define Ad 96
#define Wd 96
#define Cc 24
#define Bq 8
#define BCn 192
#define AW 9216
#define CHUNKS 6
#define CROWS 16
#define Fh 32

#define STPB 384
#define MTPB 384

#define SETR (BCn * 768)
#define SETC (BCn * 768)
#define SETT (BCn * 8)
#define SETM (BCn * 32)

// ---------------- device scratch ----------------
__device__ float    g_h[(size_t)BCn * Fh * AW];   // h: [bc][f][pos] fp32
__device__ double   g_rowsum[2 * SETR];
__device__ double   g_colsum[2 * SETC];
__device__ double   g_tot[2 * SETT];
__device__ unsigned g_hmax[2 * SETM];             // encoded-uint max
__device__ double   g_sq[BCn * Fh];
__device__ double   g_mean[BCn];
__device__ double   g_istd[BCn];
// PWL tables for mlp0: 129 segments
__device__ double g_tsort[128];
__device__ double g_A[129][32];
__device__ double g_B[129][32];

// ---------------- packed fp32 helpers (asm: fast-math-proof) ----------------
#define NEG1P 0xBF800000BF800000ULL   /* {-1.0f, -1.0f} */
#define SGN2  0x8000000080000000ULL

__device__ __forceinline__ float lof(ull v) { return __uint_as_float((unsigned)v); }
__device__ __forceinline__ float hif(ull v) { return __uint_as_float((unsigned)(v >> 32)); }
__device__ __forceinline__ ull dup2(float x) { ull r; asm("mov.b64 %0,{%1,%1};" : "=l"(r) : "f"(x)); return r; }
__device__ __forceinline__ ull mk2(float x, float y) { ull r; asm("mov.b64 %0,{%1,%2};" : "=l"(r) : "f"(x), "f"(y)); return r; }
__device__ __forceinline__ ull neg2(ull a) { return a ^ SGN2; }
__device__ __forceinline__ ull mul2(ull a, ull b) {
    ull d; asm("mul.rn.f32x2 %0,%1,%2;" : "=l"(d) : "l"(a), "l"(b)); return d;
}
__device__ __forceinline__ ull add2(ull a, ull b) {
    ull d; asm("add.rn.f32x2 %0,%1,%2;" : "=l"(d) : "l"(a), "l"(b)); return d;
}
__device__ __forceinline__ ull fma2(ull a, ull b, ull c) {
    ull d; asm("fma.rn.f32x2 %0,%1,%2,%3;" : "=l"(d) : "l"(a), "l"(b), "l"(c)); return d;
}

// df MAC, Knuth TwoSum (exact; precompute paths)
__device__ __forceinline__ void df_mac(ull& S, ull& L, ull rh, ull rl, ull w) {
    const ull N1 = NEG1P;
    ull p  = mul2(rh, w);
    ull e  = fma2(rh, w, neg2(p));
    e      = fma2(rl, w, e);
    ull s1 = add2(S, p);
    ull ap = fma2(p, N1, s1);
    ull bp = fma2(ap, N1, s1);
    ull ea = fma2(ap, N1, S);
    ull eb = fma2(bp, N1, p);
    ull er = add2(ea, eb);
    L      = add2(L, er);
    L      = add2(L, e);
    S      = s1;
}
// df MAC, Fast2Sum compensation (8 ops; inner-loop L2).
// EXACT TwoProd residual is load-bearing (R12 post-mortem);
// only the addition compensation is approximate (loss when |p|>|S|: rare).
__device__ __forceinline__ void df_macf(ull& S, ull& L, ull rh, ull rl, ull w) {
    const ull N1 = NEG1P;
    ull p  = mul2(rh, w);
    ull e  = fma2(rh, w, neg2(p));
    e      = fma2(rl, w, e);
    ull s1 = add2(S, p);
    ull z  = fma2(S, N1, s1);    // s1 - S
    ull e2 = fma2(z, N1, p);     // p - z
    L      = add2(L, e2);
    L      = add2(L, e);
    S      = s1;
}

__device__ __forceinline__ unsigned encf(float x) {
    int i = __float_as_int(x);
    return (i >= 0) ? ((unsigned)i | 0x80000000u) : ~(unsigned)i;
}
__device__ __forceinline__ float decf(unsigned u) {
    int i = (u & 0x80000000u) ? (int)(u & 0x7fffffffu) : ~(int)u;
    return __int_as_float(i);
}
#define ENC_NEGMAX 0x00800000u
#define ENC_ZERO   0x80000000u

__device__ __forceinline__ double warpsumd(double v) {
    v += __shfl_xor_sync(0xffffffffu, v, 16);
    v += __shfl_xor_sync(0xffffffffu, v, 8);
    v += __shfl_xor_sync(0xffffffffu, v, 4);
    v += __shfl_xor_sync(0xffffffffu, v, 2);
    v += __shfl_xor_sync(0xffffffffu, v, 1);
    return v;
}
__device__ __forceinline__ float warpmaxf(float v) {
    v = fmaxf(v, __shfl_xor_sync(0xffffffffu, v, 16));
    v = fmaxf(v, __shfl_xor_sync(0xffffffffu, v, 8));
    v = fmaxf(v, __shfl_xor_sync(0xffffffffu, v, 4));
    v = fmaxf(v, __shfl_xor_sync(0xffffffffu, v, 2));
    v = fmaxf(v, __shfl_xor_sync(0xffffffffu, v, 1));
    return v;
}

// Accurate fp32 sin (1-2 ulp), fast-math-proof.
__device__ __forceinline__ float sin_acc(float x) {
    float n = rintf(x * 0.318309886183790672f);
    float r = fmaf(n, -3.140625f, x);
    r = fmaf(n, -9.67502593994140625e-4f, r);
    r = fmaf(n, -1.50995799097837643e-7f, r);
    float r2 = r * r;
    float p = fmaf(r2, 2.60831598e-06f, -1.98106907e-04f);
    p = fmaf(r2, p, 8.33330786e-03f);
    p = fmaf(r2, p, -1.66666597e-01f);
    float s = fmaf(r * r2, p, r);
    int ni = (int)n;
    return __int_as_float(__float_as_int(s) ^ ((ni & 1) << 31));
}
// Packed pair sin: lane-wise IDENTICAL RN ops to sin_acc (bit-identical results).
__device__ __forceinline__ ull sin_acc2(float x0, float x1) {
    float n0 = rintf(x0 * 0.318309886183790672f);
    float n1 = rintf(x1 * 0.318309886183790672f);
    ull xv = mk2(x0, x1);
    ull nv = mk2(n0, n1);
    ull r = fma2(nv, dup2(-3.140625f), xv);
    r = fma2(nv, dup2(-9.67502593994140625e-4f), r);
    r = fma2(nv, dup2(-1.50995799097837643e-7f), r);
    ull r2 = mul2(r, r);
    ull p = fma2(r2, dup2(2.60831598e-06f), dup2(-1.98106907e-04f));
    p = fma2(r2, p, dup2(8.33330786e-03f));
    p = fma2(r2, p, dup2(-1.66666597e-01f));
    ull s = fma2(mul2(r, r2), p, r);
    unsigned m0 = ((unsigned)((int)n0 & 1)) << 31;
    unsigned m1 = ((unsigned)((int)n1 & 1)) << 31;
    return s ^ (((ull)m1 << 32) | (ull)m0);
}

// ---------------- per-matrix mean / inv-std + g_sq zero ----------------
__global__ void stats_kernel(const float* __restrict__ x,
                             const int* __restrict__ rlp, const int* __restrict__ clp) {
    int bc = blockIdx.x, tid = threadIdx.x;
    int rl = rlp[bc], cl = clp[bc];
    double s = 0.0, s2 = 0.0;
    const float* xp = x + (size_t)bc * AW;
    for (int p = tid; p < AW; p += 256) {
        int a = p / Wd, w = p - a * Wd;
        if (a < rl && w < cl) { double v = (double)xp[p]; s += v; s2 += v * v; }
    }
    __shared__ double sh[256], sh2[256];
    sh[tid] = s; sh2[tid] = s2;
    __syncthreads();
    for (int o = 128; o; o >>= 1) {
        if (tid < o) { sh[tid] += sh[tid + o]; sh2[tid] += sh2[tid + o]; }
        __syncthreads();
    }
    if (tid == 0) {
        double n = (double)rl * (double)cl;
        double mean = sh[0] / n;
        double var = (sh2[0] - n * mean * mean) / (n - 1.0);
        g_mean[bc] = mean;
        g_istd[bc] = 1.0 / fmax(sqrt(fmax(var, 0.0)), 1e-12);
    }
    if (tid < 32) g_sq[bc * 32 + tid] = 0.0;
}

// ---------------- zero one accumulator set ----------------
__global__ void zero_set(int s) {
    int i = blockIdx.x * 256 + threadIdx.x;   // 576*256 = SETC
    g_colsum[s * SETC + i] = 0.0;
    if (i < SETT) g_tot[s * SETT + i] = 0.0;
    if (i < SETM) g_hmax[s * SETM + i] = ENC_NEGMAX;
}

// ---------------- mlp0 PWL precompute ----------------
__global__ void mlp0_pre(const float* __restrict__ w01, const float* __restrict__ b01,
                         const float* __restrict__ w2, const float* __restrict__ b2) {
    __shared__ double tval[128];
    __shared__ int order[128];
    __shared__ double tsort[128];
    int j = threadIdx.x;   // 128 threads
    double wj = (double)w01[j], bj = (double)b01[j];
    double t = (wj != 0.0) ? (-bj / wj) : DBL_MAX;
    tval[j] = t;
    __syncthreads();
    int rank = 0;
    for (int k = 0; k < 128; k++) {
        double tk = tval[k];
        rank += (tk < t) || (tk == t && k < j);
    }
    order[rank] = j;
    tsort[rank] = t;
    __syncthreads();
    g_tsort[j] = tsort[j];
    if (j < 32) {
        int f = j;
        double A = 0.0, B = (double)b2[f];
        for (int k = 0; k < 128; k++) {
            double wk = (double)w01[k], bk = (double)b01[k];
            if (wk < 0.0 || (wk == 0.0 && bk > 0.0)) {
                double w2v = (double)w2[k * 32 + f];
                A += wk * w2v; B += bk * w2v;
            }
        }
        g_A[0][f] = A; g_B[0][f] = B;
        for (int s = 1; s <= 128; s++) {
            int k = order[s - 1];
            double wk = (double)w01[k], bk = (double)b01[k];
            double w2v = (double)w2[k * 32 + f];
            if (wk > 0.0)      { A += wk * w2v; B += bk * w2v; }
            else if (wk < 0.0) { A -= wk * w2v; B -= bk * w2v; }
            g_A[s][f] = A; g_B[s][f] = B;
        }
    }
}

// ---------------- mlp0 eval: PWL + fused stack-0 reduction epilogue (writes set 0) ----------------
#define EVD_PWL (128 + 2 * 129 * 33)
#define EVD_ROW EVD_PWL
#define EVD_COL (EVD_ROW + 128)
#define EVD_TOT (EVD_COL + 768)
#define EVD_MAX (EVD_TOT + 8)
#define EV_SMEM ((EVD_MAX + 16) * 8)
__global__ void __launch_bounds__(MTPB, 1)
mlp0_eval(const float* __restrict__ x,
          const int* __restrict__ rlp, const int* __restrict__ clp) {
    int bid = blockIdx.x;
    int bc = bid / CHUNKS, chunk = bid - (bid / CHUNKS) * CHUNKS;
    int a0 = chunk * CROWS;
    int tid = threadIdx.x, lane = tid & 31;
    int rl = rlp[bc], cl = clp[bc];
    if (a0 >= rl) {
        if (tid < 32) atomicMax(&g_hmax[bc * 32 + tid], ENC_ZERO);
        return;
    }
    extern __shared__ double smd[];
    double* s_t = smd;
    double* s_A = smd + 128;
    double* s_B = s_A + 129 * 33;
    double*   s_erow = smd + EVD_ROW;
    double*   s_ecol = smd + EVD_COL;
    double*   s_etot = smd + EVD_TOT;
    unsigned* s_emax = (unsigned*)(smd + EVD_MAX);
    bool hasInv = (rl < a0 + CROWS) || (cl < Wd);
    for (int e = tid; e < 129 * 32; e += MTPB) {
        int s = e >> 5, f = e & 31;
        s_A[s * 33 + f] = g_A[s][f];
        s_B[s * 33 + f] = g_B[s][f];
    }
    if (tid < 128) s_t[tid] = g_tsort[tid];
    for (int e = tid; e < 128; e += MTPB) s_erow[e] = 0.0;
    for (int e = tid; e < 768; e += MTPB) s_ecol[e] = 0.0;
    if (tid < 8) s_etot[tid] = 0.0;
    if (tid < 32) s_emax[tid] = hasInv ? ENC_ZERO : ENC_NEGMAX;
    __syncthreads();

    double meand = g_mean[bc], istdd = g_istd[bc];
    const float* xp = x + (size_t)bc * AW + a0 * Wd;
    float* hbc = g_h + (size_t)bc * Fh * AW + a0 * Wd;

    double totg[8];
    float rmax[32];
#pragma unroll
    for (int k = 0; k < 8; k++) totg[k] = 0.0;
#pragma unroll
    for (int f = 0; f < 32; f++) rmax[f] = -FLT_MAX;

    for (int it = 0; it < 4; ++it) {
        int p = it * MTPB + tid;
        int al = p / Wd, w = p - al * Wd;
        bool valid = (a0 + al < rl) && (w < cl);
        if (!__any_sync(0xffffffffu, valid)) continue;
        float xnf = valid ? (float)(((double)xp[p] - meand) * istdd) : 0.f;
        double xd = (double)xnf;
        int lo = 0, hi = 128;
#pragma unroll
        for (int st = 0; st < 7; st++) {
            int mid = (lo + hi) >> 1;
            bool c = s_t[mid] < xd;
            lo = c ? mid + 1 : lo;
            hi = c ? hi : mid;
        }
        const double* Ar = s_A + lo * 33;
        const double* Br = s_B + lo * 33;
        float hv[32];
#pragma unroll
        for (int f = 0; f < 32; f++) {
            double o = fma(Ar[f], xd, Br[f]);
            hv[f] = valid ? (float)o : 0.f;
            hbc[(size_t)f * AW + p] = hv[f];
        }
#pragma unroll
        for (int k = 0; k < 8; k++) {
            ull y12 = sin_acc2(hv[4 * k + 1], hv[4 * k + 2]);
            float y1 = lof(y12), y2 = hif(y12);
            float y3 = sin_acc(hv[4 * k + 3]);
            totg[k] += (double)y3;
            atomicAdd(&s_ecol[k * 96 + w], (double)y2);
            double srw = warpsumd((double)y1);
            if (lane == 0) atomicAdd(&s_erow[al * 8 + k], srw);
        }
#pragma unroll
        for (int f = 0; f < 32; f++) rmax[f] = fmaxf(rmax[f], hv[f]);
    }
#pragma unroll
    for (int k = 0; k < 8; k++) {
        double s = warpsumd(totg[k]);
        if (lane == 0) atomicAdd(&s_etot[k], s);
    }
#pragma unroll
    for (int f = 0; f < 32; f++) {
        float m = warpmaxf(rmax[f]);
        if (lane == 0) atomicMax(&s_emax[f], encf(m));
    }
    __syncthreads();
    for (int e = tid; e < 128; e += MTPB) g_rowsum[bc * 768 + a0 * 8 + e] = s_erow[e];
    for (int e = tid; e < 768; e += MTPB) {
        int wi2 = e >> 3, kk = e & 7;
        atomicAdd(&g_colsum[bc * 768 + e], s_ecol[kk * 96 + wi2]);
    }
    if (tid < 8) atomicAdd(&g_tot[bc * 8 + tid], s_etot[tid]);
    if (tid < 32) atomicMax(&g_hmax[bc * 32 + tid], s_emax[tid]);
}

// ---------------- one equivariant stack (df, R14 shape) + fused epilogue ----------------
#define SK_W1   0        /* 8192 */
#define SK_W2   8192     /* 4096 */
#define SK_CROW 12288    /* 16*65 ull2 = 4160 floats */
#define SK_COLT 16448    /* 96*65 ull2 = 24960 floats */
#define SK_CSD  41408    /* float2 x768 = 1536 */
#define SK_RSD  42944    /* float2 x128 = 256 */
#define SK_BASE 43200    /* double x128 = 256 */
#define SK_TT   43456    /* double x8 = 16 */
#define SK_HM   43472    /* 32 */
#define SK_B1   43504    /* 128 */
#define SK_B2   43632    /* 32 */
#define SE_ROW  43664    /* double x128 = 256 */
#define SE_COL  43920    /* double x768 = 1536 */
#define SE_TOT  45456    /* double x8 = 16 */
#define SE_MAX  45472    /* 32 u32 */
#define SK_W1E0 45504    /* 64*8 ull = 1024 floats */
#define SK_TOTF 46528
#define STACK_SMEM (SK_TOTF * 4)

template <bool LAST>
__global__ void __launch_bounds__(STPB, 1)
stack_kernel(const float* __restrict__ w1g, const float* __restrict__ b1g,
             const float* __restrict__ w2g, const float* __restrict__ b2g,
             const int* __restrict__ rlp, const int* __restrict__ clp, int ri) {
    int bid = blockIdx.x;
    int bc = bid / CHUNKS, chunk = bid - (bid / CHUNKS) * CHUNKS;
    int a0 = chunk * CROWS;
    int tid = threadIdx.x, lane = tid & 31;
    int rl = rlp[bc], cl = clp[bc];
    int wi = 1 - ri;
    if (a0 >= rl) {
        if (!LAST && tid < 32) atomicMax(&g_hmax[wi * SETM + bc * 32 + tid], ENC_ZERO);
        return;
    }
    int b = bc / Cc;

    extern __shared__ float smf[];
    float*      w1s  = smf + SK_W1;
    float*      w2s  = smf + SK_W2;
    ulonglong2* crw  = (ulonglong2*)(smf + SK_CROW);
    ulonglong2* ctw  = (ulonglong2*)(smf + SK_COLT);
    float2*     csd  = (float2*)(smf + SK_CSD);
    float2*     rsd  = (float2*)(smf + SK_RSD);
    double*     based= (double*)(smf + SK_BASE);
    double*     ttd  = (double*)(smf + SK_TT);
    float*      hmf  = smf + SK_HM;
    float*      b1f  = smf + SK_B1;
    float*      b2f  = smf + SK_B2;
    double*     s_erow = (double*)(smf + SE_ROW);
    double*     s_ecol = (double*)(smf + SE_COL);
    double*     s_etot = (double*)(smf + SE_TOT);
    unsigned*   s_emax = (unsigned*)(smf + SE_MAX);
    ull*        w1e0 = (ull*)(smf + SK_W1E0);   // [j2][k]
    bool hasInv = (rl < a0 + CROWS) || (cl < Wd);

    for (int e = tid; e < 8192; e += STPB) w1s[e] = w1g[e];
    for (int e = tid; e < 4096; e += STPB) w2s[e] = w2g[e];
    if (tid < 128) b1f[tid] = b1g[tid];
    if (tid < 32)  b2f[tid] = b2g[tid];
    for (int e = tid; e < 768; e += STPB) {
        double v = g_colsum[ri * SETC + bc * 768 + e];
        float hi = (float)v;
        csd[e] = make_float2(hi, (float)(v - (double)hi));
    }
    if (tid < 128) {
        double v = g_rowsum[ri * SETR + bc * 768 + a0 * 8 + tid];
        float hi = (float)v;
        rsd[tid] = make_float2(hi, (float)(v - (double)hi));
    }
    if (tid < 8) ttd[tid] = g_tot[ri * SETT + bc * 8 + tid];
    if (tid < 32) {
        float m = -FLT_MAX;
        for (int c = 0; c < Cc; c++) m = fmaxf(m, decf(g_hmax[ri * SETM + (b * Cc + c) * 32 + tid]));
        hmf[tid] = m;
    }
    if (!LAST) {
        for (int e = tid; e < 128; e += STPB) s_erow[e] = 0.0;
        for (int e = tid; e < 768; e += STPB) s_ecol[e] = 0.0;
        if (tid < 8) s_etot[tid] = 0.0;
        if (tid < 32) s_emax[tid] = hasInv ? ENC_ZERO : ENC_NEGMAX;
    } else {
        if (tid < 32) s_erow[tid] = 0.0;   // reused as s_sq
    }
    __syncthreads();
    if (tid < 128) {   // base[j] = b1 + tot-term + max-term (fp64)
        double acc = (double)b1f[tid];
#pragma unroll
        for (int k = 0; k < 8; k++) acc = fma(ttd[k], (double)w1s[(24 + k) * 128 + tid], acc);
#pragma unroll
        for (int f = 0; f < 32; f++) acc = fma((double)hmf[f], (double)w1s[(32 + f) * 128 + tid], acc);
        based[tid] = acc;
    }
    // repack w1 e0 rows: w1e0[j2*8 + k] = {w1[k][2j2], w1[k][2j2+1]}
    for (int e = tid; e < 512; e += STPB) {
        int j2 = e >> 3, k = e & 7;
        w1e0[e] = ((const ull*)(w1s + k * 128))[j2];
    }
    __syncthreads();
    // colt df: [w][j] = sum_k cs_df[w][k] * w1[16+k][j] (exact Knuth)
    for (int e = tid; e < 6144; e += STPB) {
        int w = e >> 6, j2 = e & 63;
        ull S = 0ull, L = 0ull;
#pragma unroll
        for (int k = 0; k < 8; k++) {
            float2 c = csd[w * 8 + k];
            df_mac(S, L, dup2(c.x), dup2(c.y), ((const ull*)(w1s + (16 + k) * 128))[j2]);
        }
        ctw[w * 65 + j2] = make_ulonglong2(S, L);
    }
    // crow df: [r][j] = base + sum_k rs_df[r][k] * w1[8+k][j] (exact Knuth)
    for (int e = tid; e < 1024; e += STPB) {
        int r = e >> 6, j2 = e & 63;
        double b0 = based[2 * j2], b1v = based[2 * j2 + 1];
        float bh0 = (float)b0, bh1 = (float)b1v;
        ull S = mk2(bh0, bh1);
        ull L = mk2((float)(b0 - (double)bh0), (float)(b1v - (double)bh1));
#pragma unroll
        for (int k = 0; k < 8; k++) {
            float2 rr = rsd[r * 8 + k];
            df_mac(S, L, dup2(rr.x), dup2(rr.y), ((const ull*)(w1s + (8 + k) * 128))[j2]);
        }
        crw[r * 65 + j2] = make_ulonglong2(S, L);
    }
    __syncthreads();

    float* hbc = g_h + (size_t)bc * Fh * AW + a0 * Wd;
    const ull* b2p = (const ull*)b2f;
    const ull N1 = NEG1P;

    double totg[8];
    float rmax[32];
    ull sqacc[16];
    if (!LAST) {
#pragma unroll
        for (int k = 0; k < 8; k++) totg[k] = 0.0;
#pragma unroll
        for (int f = 0; f < 32; f++) rmax[f] = -FLT_MAX;
    } else {
#pragma unroll
        for (int f2 = 0; f2 < 16; f2++) sqacc[f2] = 0ull;
    }

    for (int it = 0; it < 4; ++it) {
        int p = it * STPB + tid;
        int al = p / Wd, w = p - al * Wd;
        bool valid = (a0 + al < rl) && (w < cl);
        if (!__any_sync(0xffffffffu, valid)) continue;

        float hf[32];
#pragma unroll
        for (int f = 0; f < 32; f++) hf[f] = hbc[(size_t)f * AW + p];

        ull e0d[8];
#pragma unroll
        for (int kk2 = 0; kk2 < 4; kk2++) {   // packed sin pairs (bit-identical per lane)
            ull sp = sin_acc2(hf[8 * kk2], hf[8 * kk2 + 4]);
            e0d[2 * kk2]     = dup2(lof(sp));
            e0d[2 * kk2 + 1] = dup2(hif(sp));
        }
        // o init: exact TwoSum(h, b2)  (skip + b2)
        ull oS[16], oL[16];
#pragma unroll
        for (int f2 = 0; f2 < 16; f2++) {
            ull hp2 = mk2(hf[2 * f2], hf[2 * f2 + 1]);
            ull bv = b2p[f2];
            ull s1 = add2(hp2, bv);
            ull ap = fma2(bv, N1, s1);
            ull bp = fma2(ap, N1, s1);
            ull ea = fma2(ap, N1, hp2);
            ull eb = fma2(bp, N1, bv);
            oS[f2] = s1;
            oL[f2] = add2(ea, eb);
        }

        const ulonglong2* crp = crw + al * 65;
        const ulonglong2* ctp = ctw + w * 65;

#pragma unroll 2
        for (int j2 = 0; j2 < 64; j2++) {
            ulonglong2 cr = crp[j2];
            ulonglong2 ct = ctp[j2];
            ull S = cr.x, L = cr.y;
            // L1 e0 terms seeded with colt.hi (plain packed fp32 chain; same rounding
            // count as before, colt.hi enters exactly; colt.lo preserved below)
            const ulonglong2* we = (const ulonglong2*)(w1e0 + j2 * 8);
            ulonglong2 wv0 = we[0], wv1 = we[1], wv2 = we[2], wv3 = we[3];
            ull acc = fma2(e0d[0], wv0.x, ct.x);
            acc = fma2(e0d[1], wv0.y, acc);
            acc = fma2(e0d[2], wv1.x, acc);
            acc = fma2(e0d[3], wv1.y, acc);
            acc = fma2(e0d[4], wv2.x, acc);
            acc = fma2(e0d[5], wv2.y, acc);
            acc = fma2(e0d[6], wv3.x, acc);
            acc = fma2(e0d[7], wv3.y, acc);
            // Knuth merge of acc into (S,L), then fold in colt.lo
            {
                ull s1 = add2(S, acc);
                ull ap = fma2(acc, N1, s1);
                ull bp = fma2(ap, N1, s1);
                ull ea = fma2(ap, N1, S);
                ull eb = fma2(bp, N1, acc);
                ull er = add2(ea, eb);
                L = add2(L, er);
                L = add2(L, ct.y);
                S = s1;
            }
            ull rsum = add2(S, L);
            ull tz = fma2(rsum, N1, S);
            ull rlo = add2(tz, L);
            float rh0 = lof(rsum), rh1 = hif(rsum);
            float rl0 = lof(rlo),  rl1 = hif(rlo);
            if (rh0 + rl0 <= 0.f) { rh0 = 0.f; rl0 = 0.f; }
            if (rh1 + rl1 <= 0.f) { rh1 = 0.f; rl1 = 0.f; }
            {
                ull rhd = dup2(rh0), rld = dup2(rl0);
                const ulonglong2* wr2 = (const ulonglong2*)(w2s + (2 * j2) * 32);
#pragma unroll
                for (int q = 0; q < 8; q++) {
                    ulonglong2 wv = wr2[q];
                    df_macf(oS[2 * q],     oL[2 * q],     rhd, rld, wv.x);
                    df_macf(oS[2 * q + 1], oL[2 * q + 1], rhd, rld, wv.y);
                }
            }
            {
                ull rhd = dup2(rh1), rld = dup2(rl1);
                const ulonglong2* wr2 = (const ulonglong2*)(w2s + (2 * j2 + 1) * 32);
#pragma unroll
                for (int q = 0; q < 8; q++) {
                    ulonglong2 wv = wr2[q];
                    df_macf(oS[2 * q],     oL[2 * q],     rhd, rld, wv.x);
                    df_macf(oS[2 * q + 1], oL[2 * q + 1], rhd, rld, wv.y);
                }
            }
        }
        ull vv[16];
#pragma unroll
        for (int f2 = 0; f2 < 16; f2++) {
            ull v = add2(oS[f2], oL[f2]);
            vv[f2] = valid ? v : 0ull;
        }
        if (!LAST) {
#pragma unroll
            for (int f2 = 0; f2 < 16; f2++) {
                hbc[(size_t)(2 * f2) * AW + p]     = lof(vv[f2]);
                hbc[(size_t)(2 * f2 + 1) * AW + p] = hif(vv[f2]);
            }
#pragma unroll
            for (int k = 0; k < 8; k++) {
                ull y12 = sin_acc2(hif(vv[2 * k]), lof(vv[2 * k + 1]));
                float y1 = lof(y12), y2 = hif(y12);
                float y3 = sin_acc(hif(vv[2 * k + 1]));
                totg[k] += (double)y3;
                atomicAdd(&s_ecol[k * 96 + w], (double)y2);
                double srw = warpsumd((double)y1);
                if (lane == 0) atomicAdd(&s_erow[al * 8 + k], srw);
            }
#pragma unroll
            for (int f2 = 0; f2 < 16; f2++) {
                rmax[2 * f2]     = fmaxf(rmax[2 * f2],     lof(vv[f2]));
                rmax[2 * f2 + 1] = fmaxf(rmax[2 * f2 + 1], hif(vv[f2]));
            }
        } else {
#pragma unroll
            for (int f2 = 0; f2 < 16; f2++) sqacc[f2] = fma2(vv[f2], vv[f2], sqacc[f2]);
        }
    }
    if (!LAST) {
#pragma unroll
        for (int k = 0; k < 8; k++) {
            double s = warpsumd(totg[k]);
            if (lane == 0) atomicAdd(&s_etot[k], s);
        }
#pragma unroll
        for (int f = 0; f < 32; f++) {
            float m = warpmaxf(rmax[f]);
            if (lane == 0) atomicMax(&s_emax[f], encf(m));
        }
        __syncthreads();
        for (int e = tid; e < 128; e += STPB) g_rowsum[wi * SETR + bc * 768 + a0 * 8 + e] = s_erow[e];
        for (int e = tid; e < 768; e += STPB) {
            int wi2 = e >> 3, kk = e & 7;
            atomicAdd(&g_colsum[wi * SETC + bc * 768 + e], s_ecol[kk * 96 + wi2]);
        }
        if (tid < 8) atomicAdd(&g_tot[wi * SETT + bc * 8 + tid], s_etot[tid]);
        if (tid < 32) atomicMax(&g_hmax[wi * SETM + bc * 32 + tid], s_emax[tid]);
    } else {
#pragma unroll
        for (int f2 = 0; f2 < 16; f2++) {
            double slo = warpsumd((double)lof(sqacc[f2]));
            double shi = warpsumd((double)hif(sqacc[f2]));
            if (lane == 0) {
                atomicAdd(&s_erow[2 * f2], slo);
                atomicAdd(&s_erow[2 * f2 + 1], shi);
            }
        }
        __syncthreads();
        if (tid < 32) atomicAdd(&g_sq[bc * 32 + tid], s_erow[tid]);
    }
}

// ---------------- output head (double) ----------------
__global__ void out_kernel(const int* __restrict__ rlp, const int* __restrict__ clp,
                           const float* __restrict__ w1, const float* __restrict__ b1,
                           const float* __restrict__ w2, const float* __restrict__ b2,
                           float* __restrict__ out) {
    int tid = threadIdx.x;
    __shared__ double s_h[Bq][32];
    __shared__ double s_r[128];
    int b = tid >> 5, f = tid & 31;
    double acc = 0.0;
    for (int c = 0; c < Cc; c++) {
        int bc = b * Cc + c;
        double n = (double)(rlp[bc] * clp[bc]);
        double sq = fmax(g_sq[bc * 32 + f], 1e-20);
        acc += sqrt(sq / fmax(n, 1e-12));
    }
    s_h[b][f] = acc / (double)Cc;
    __syncthreads();
    for (int bb = 0; bb < Bq; bb++) {
        if (tid < 128) {
            double r = (double)b1[tid];
            for (int ff = 0; ff < 32; ff++) r = fma(s_h[bb][ff], (double)w1[ff * 128 + tid], r);
            s_r[tid] = fmax(r, 0.0);
        }
        __syncthreads();
        if (tid < 2) {
            double o = (double)b2[tid];
            for (int j = 0; j < 128; j++) o = fma(s_r[j], (double)w2[j * 2 + tid], o);
            out[bb * 2 + tid] = (float)(8.0 * tanh(o));
        }
        __syncthreads();
    }
}

// ---------------- host ----------------
extern "C" void kernel_launch(void* const* d_in, const int* in_sizes, int n_in,
                              void* d_out, int out_size) {
    (void)in_sizes; (void)n_in; (void)out_size;
    const float* x    = (const float*)d_in[0];
    const int*   rl   = (const int*)d_in[1];
    const int*   cl   = (const int*)d_in[2];
    const float* t0w1 = (const float*)d_in[3];
    const float* t0b1 = (const float*)d_in[4];
    const float* t0w2 = (const float*)d_in[5];
    const float* t0b2 = (const float*)d_in[6];
    const float* tw1  = (const float*)d_in[7];
    const float* tb1  = (const float*)d_in[8];
    const float* tw2  = (const float*)d_in[9];
    const float* tb2  = (const float*)d_in[10];
    const float* ow1  = (const float*)d_in[11];
    const float* ob1  = (const float*)d_in[12];
    const float* ow2  = (const float*)d_in[13];
    const float* ob2  = (const float*)d_in[14];

    cudaFuncSetAttribute(stack_kernel<false>, cudaFuncAttributeMaxDynamicSharedMemorySize, STACK_SMEM);
    cudaFuncSetAttribute(stack_kernel<true>,  cudaFuncAttributeMaxDynamicSharedMemorySize, STACK_SMEM);
    cudaFuncSetAttribute(mlp0_eval, cudaFuncAttributeMaxDynamicSharedMemorySize, EV_SMEM);

    stats_kernel<<<BCn, 256>>>(x, rl, cl);
    mlp0_pre<<<1, 128>>>(t0w1, t0b1, t0w2, t0b2);
    zero_set<<<576, 256>>>(0);
    zero_set<<<576, 256>>>(1);
    mlp0_eval<<<BCn * CHUNKS, MTPB, EV_SMEM>>>(x, rl, cl);   // writes set 0

    // stack i reads set (i&1), writes set 1-(i&1)
    stack_kernel<false><<<BCn * CHUNKS, STPB, STACK_SMEM>>>(
        tw1, tb1, tw2, tb2, rl, cl, 0);
    zero_set<<<576, 256>>>(0);
    stack_kernel<false><<<BCn * CHUNKS, STPB, STACK_SMEM>>>(
        tw1 + 8192, tb1 + 128, tw2 + 4096, tb2 + 32, rl, cl, 1);
    zero_set<<<576, 256>>>(1);
    stack_kernel<false><<<BCn * CHUNKS, STPB, STACK_SMEM>>>(
        tw1 + 2 * 8192, tb1 + 2 * 128, tw2 + 2 * 4096, tb2 + 2 * 32, rl, cl, 0);
    stack_kernel<true><<<BCn * CHUNKS, STPB, STACK_SMEM>>>(
        tw1 + 3 * 8192, tb1 + 3 * 128, tw2 + 3 * 4096, tb2 + 3 * 32, rl, cl, 1);

    out_kernel<<<1, 256>>>(rl, cl, ow1, ob1, ow2, ob2, (float*)d_out);
}